// round 3
// baseline (speedup 1.0000x reference)
#include <cuda_runtime.h>
#include <math.h>

#define BATCH 16
#define CCH   256
#define ICH   128
#define HW    4096
#define NV    2048

#define BM 128
#define BN 128
#define BK 16

// ---------------- scratch (device globals; no allocation allowed) ----------
__device__ float g_phi  [(size_t)BATCH * ICH * HW];
__device__ float g_theta[(size_t)BATCH * ICH * HW];
__device__ float g_gp   [(size_t)BATCH * ICH * HW];
__device__ float g_o    [(size_t)BATCH * ICH * HW];
__device__ float g_s    [(size_t)BATCH * NV * NV];     // 268 MB score scratch
__device__ float g_cmax [BATCH * NV];
__device__ float g_cinv [BATCH * NV];

// ============================================================================
// Kernel 1: projections.  C[m,n] = sum_k W[m,k] * X[k,n] + bias[m]
// M=128, N=4096, K=256, one of {phi,theta,g} per blockIdx.z%3.
// ============================================================================
__global__ __launch_bounds__(256) void proj_kernel(
    const float* __restrict__ x,
    const float* __restrict__ w0, const float* __restrict__ b0,
    const float* __restrict__ w1, const float* __restrict__ b1,
    const float* __restrict__ w2, const float* __restrict__ b2)
{
    const int z = blockIdx.z;
    const int batch = z / 3;
    const int pj = z - batch * 3;
    const float* W    = (pj == 0) ? w0 : (pj == 1) ? w1 : w2;
    const float* bias = (pj == 0) ? b0 : (pj == 1) ? b1 : b2;
    float* out = ((pj == 0) ? g_phi : (pj == 1) ? g_theta : g_gp)
                 + (size_t)batch * ICH * HW;
    const float* Bmat = x + (size_t)batch * CCH * HW;

    const int K = CCH;   // 256
    const int N = HW;    // 4096
    const int n0 = blockIdx.x * BN;

    __shared__ __align__(16) float As[BK][BM + 4];   // transposed W tile, padded
    __shared__ __align__(16) float Bs[BK][BN];

    const int tid = threadIdx.x;
    const int tx = tid & 15, ty = tid >> 4;

    float acc[8][8];
#pragma unroll
    for (int i = 0; i < 8; i++)
#pragma unroll
        for (int j = 0; j < 8; j++) acc[i][j] = 0.f;

    for (int k0 = 0; k0 < K; k0 += BK) {
#pragma unroll
        for (int u = 0; u < 2; u++) {                 // A tile: 128x16, transpose
            int idx = tid + u * 256;
            int r = idx >> 2, cq = idx & 3;
            float4 v = *(const float4*)&W[r * K + k0 + cq * 4];
            As[cq*4+0][r] = v.x; As[cq*4+1][r] = v.y;
            As[cq*4+2][r] = v.z; As[cq*4+3][r] = v.w;
        }
#pragma unroll
        for (int u = 0; u < 2; u++) {                 // B tile: 16x128, direct
            int idx = tid + u * 256;
            int kk = idx >> 5, nq = idx & 31;
            *(float4*)&Bs[kk][nq*4] =
                *(const float4*)&Bmat[(size_t)(k0+kk)*N + n0 + nq*4];
        }
        __syncthreads();
#pragma unroll
        for (int kk = 0; kk < BK; kk++) {
            float a[8], b[8];
            *(float4*)&a[0] = *(const float4*)&As[kk][ty*4];
            *(float4*)&a[4] = *(const float4*)&As[kk][64 + ty*4];
            *(float4*)&b[0] = *(const float4*)&Bs[kk][tx*4];
            *(float4*)&b[4] = *(const float4*)&Bs[kk][64 + tx*4];
#pragma unroll
            for (int i = 0; i < 8; i++)
#pragma unroll
                for (int j = 0; j < 8; j++) acc[i][j] += a[i] * b[j];
        }
        __syncthreads();
    }
#pragma unroll
    for (int i = 0; i < 8; i++) {
        int m = (i < 4) ? (ty*4 + i) : (64 + ty*4 + i - 4);
        float bv = bias[m];
        float4 v0 = make_float4(acc[i][0]+bv, acc[i][1]+bv, acc[i][2]+bv, acc[i][3]+bv);
        float4 v1 = make_float4(acc[i][4]+bv, acc[i][5]+bv, acc[i][6]+bv, acc[i][7]+bv);
        *(float4*)&out[(size_t)m*N + n0 + tx*4]      = v0;
        *(float4*)&out[(size_t)m*N + n0 + 64 + tx*4] = v1;
    }
}

// ============================================================================
// Kernel 2: scores s[n,m] = sum_k theta_v[k,n] * phi_v[k,m]   (TN GEMM)
// M=N=2048, K=256. theta/phi flat buffers reinterpreted as [256][2048].
// ============================================================================
__global__ __launch_bounds__(256) void scores_kernel()
{
    const int b = blockIdx.z;
    const float* A  = g_theta + (size_t)b * ICH * HW;  // [256][2048]
    const float* Bp = g_phi   + (size_t)b * ICH * HW;  // [256][2048]
    float* S = g_s + (size_t)b * NV * NV;

    const int m0 = blockIdx.y * BM;   // n rows
    const int n0 = blockIdx.x * BN;   // m cols

    __shared__ __align__(16) float As[BK][BM];
    __shared__ __align__(16) float Bs[BK][BN];

    const int tid = threadIdx.x;
    const int tx = tid & 15, ty = tid >> 4;

    float acc[8][8];
#pragma unroll
    for (int i = 0; i < 8; i++)
#pragma unroll
        for (int j = 0; j < 8; j++) acc[i][j] = 0.f;

    for (int k0 = 0; k0 < CCH; k0 += BK) {
#pragma unroll
        for (int u = 0; u < 2; u++) {
            int idx = tid + u * 256;
            int kk = idx >> 5, q = idx & 31;
            *(float4*)&As[kk][q*4] = *(const float4*)&A [(size_t)(k0+kk)*NV + m0 + q*4];
        }
#pragma unroll
        for (int u = 0; u < 2; u++) {
            int idx = tid + u * 256;
            int kk = idx >> 5, q = idx & 31;
            *(float4*)&Bs[kk][q*4] = *(const float4*)&Bp[(size_t)(k0+kk)*NV + n0 + q*4];
        }
        __syncthreads();
#pragma unroll
        for (int kk = 0; kk < BK; kk++) {
            float a[8], bfr[8];
            *(float4*)&a[0]   = *(const float4*)&As[kk][ty*4];
            *(float4*)&a[4]   = *(const float4*)&As[kk][64 + ty*4];
            *(float4*)&bfr[0] = *(const float4*)&Bs[kk][tx*4];
            *(float4*)&bfr[4] = *(const float4*)&Bs[kk][64 + tx*4];
#pragma unroll
            for (int i = 0; i < 8; i++)
#pragma unroll
                for (int j = 0; j < 8; j++) acc[i][j] += a[i] * bfr[j];
        }
        __syncthreads();
    }
#pragma unroll
    for (int i = 0; i < 8; i++) {
        int row = m0 + ((i < 4) ? (ty*4 + i) : (64 + ty*4 + i - 4));
        *(float4*)&S[(size_t)row*NV + n0 + tx*4]      = *(float4*)&acc[i][0];
        *(float4*)&S[(size_t)row*NV + n0 + 64 + tx*4] = *(float4*)&acc[i][4];
    }
}

// ============================================================================
// Kernel 3: per-column (m) online softmax stats over rows n.
// ============================================================================
__global__ __launch_bounds__(256) void reduce_kernel()
{
    const int b = blockIdx.y;
    const int m = blockIdx.x * 256 + threadIdx.x;
    const float* S = g_s + (size_t)b * NV * NV;

    float mx = __int_as_float(0xff800000);   // -inf
    float sm = 0.f;
    for (int n = 0; n < NV; n += 8) {
        float v[8];
#pragma unroll
        for (int q = 0; q < 8; q++) v[q] = S[(size_t)(n+q)*NV + m];
#pragma unroll
        for (int q = 0; q < 8; q++) {
            float nm = fmaxf(mx, v[q]);
            sm = sm * expf(mx - nm) + expf(v[q] - nm);
            mx = nm;
        }
    }
    g_cmax[b*NV + m] = mx;
    g_cinv[b*NV + m] = 1.0f / sm;
}

// ============================================================================
// Kernel 4: out^T[c,n] = sum_m (g_v[c,m]*cinv[m]) * exp(s[n,m]-cmax[m])
// NT GEMM: M=256 (c), N=2048 (n), K=2048 (m). exp fused into B-tile load,
// 1/colsum fused into A-tile load.
// ============================================================================
__global__ __launch_bounds__(256) void outgemm_kernel()
{
    const int b = blockIdx.z;
    const float* A    = g_gp + (size_t)b * ICH * HW;   // [256][2048], k-fast
    const float* S    = g_s  + (size_t)b * NV * NV;    // [2048(n)][2048(k)]
    const float* cmax = g_cmax + b * NV;
    const float* cinv = g_cinv + b * NV;
    float* O = g_o + (size_t)b * ICH * HW;             // [256][2048]

    const int c0 = blockIdx.y * BM;   // 0 or 128
    const int n0 = blockIdx.x * BN;

    __shared__ __align__(16) float As[BK][BM + 4];
    __shared__ __align__(16) float Bs[BK][BN + 4];

    const int tid = threadIdx.x;
    const int tx = tid & 15, ty = tid >> 4;

    float acc[8][8];
#pragma unroll
    for (int i = 0; i < 8; i++)
#pragma unroll
        for (int j = 0; j < 8; j++) acc[i][j] = 0.f;

    for (int k0 = 0; k0 < NV; k0 += BK) {
#pragma unroll
        for (int u = 0; u < 2; u++) {                 // A tile: scale + transpose
            int idx = tid + u * 256;
            int r = idx >> 2, cq = idx & 3;
            float4 v  = *(const float4*)&A[(size_t)(c0+r)*NV + k0 + cq*4];
            float4 ci = *(const float4*)&cinv[k0 + cq*4];
            As[cq*4+0][r] = v.x * ci.x; As[cq*4+1][r] = v.y * ci.y;
            As[cq*4+2][r] = v.z * ci.z; As[cq*4+3][r] = v.w * ci.w;
        }
#pragma unroll
        for (int u = 0; u < 2; u++) {                 // B tile: exp + transpose
            int idx = tid + u * 256;
            int r = idx >> 2, cq = idx & 3;
            float4 v  = *(const float4*)&S[(size_t)(n0+r)*NV + k0 + cq*4];
            float4 cm = *(const float4*)&cmax[k0 + cq*4];
            Bs[cq*4+0][r] = expf(v.x - cm.x); Bs[cq*4+1][r] = expf(v.y - cm.y);
            Bs[cq*4+2][r] = expf(v.z - cm.z); Bs[cq*4+3][r] = expf(v.w - cm.w);
        }
        __syncthreads();
#pragma unroll
        for (int kk = 0; kk < BK; kk++) {
            float a[8], bfr[8];
            *(float4*)&a[0]   = *(const float4*)&As[kk][ty*4];
            *(float4*)&a[4]   = *(const float4*)&As[kk][64 + ty*4];
            *(float4*)&bfr[0] = *(const float4*)&Bs[kk][tx*4];
            *(float4*)&bfr[4] = *(const float4*)&Bs[kk][64 + tx*4];
#pragma unroll
            for (int i = 0; i < 8; i++)
#pragma unroll
                for (int j = 0; j < 8; j++) acc[i][j] += a[i] * bfr[j];
        }
        __syncthreads();
    }
#pragma unroll
    for (int i = 0; i < 8; i++) {
        int c = c0 + ((i < 4) ? (ty*4 + i) : (64 + ty*4 + i - 4));
        *(float4*)&O[(size_t)c*NV + n0 + tx*4]      = *(float4*)&acc[i][0];
        *(float4*)&O[(size_t)c*NV + n0 + 64 + tx*4] = *(float4*)&acc[i][4];
    }
}

// ============================================================================
// Kernel 5: mask conv + bias + residual.
// C[m,n] = sum_k w_mask[m,k]*o[k,n] + b_mask[m] + x[m,n].  M=256,N=4096,K=128.
// ============================================================================
__global__ __launch_bounds__(256) void mask_kernel(
    const float* __restrict__ wm, const float* __restrict__ bm,
    const float* __restrict__ x, float* __restrict__ outp)
{
    const int b = blockIdx.z;
    const float* Bmat = g_o + (size_t)b * ICH * HW;   // [128][4096]
    const float* xr   = x   + (size_t)b * CCH * HW;
    float* O          = outp + (size_t)b * CCH * HW;

    const int K = ICH;   // 128
    const int N = HW;    // 4096
    const int m0 = blockIdx.y * BM;
    const int n0 = blockIdx.x * BN;

    __shared__ __align__(16) float As[BK][BM + 4];
    __shared__ __align__(16) float Bs[BK][BN];

    const int tid = threadIdx.x;
    const int tx = tid & 15, ty = tid >> 4;

    float acc[8][8];
#pragma unroll
    for (int i = 0; i < 8; i++)
#pragma unroll
        for (int j = 0; j < 8; j++) acc[i][j] = 0.f;

    for (int k0 = 0; k0 < K; k0 += BK) {
#pragma unroll
        for (int u = 0; u < 2; u++) {
            int idx = tid + u * 256;
            int r = idx >> 2, cq = idx & 3;
            float4 v = *(const float4*)&wm[(size_t)(m0+r)*K + k0 + cq*4];
            As[cq*4+0][r] = v.x; As[cq*4+1][r] = v.y;
            As[cq*4+2][r] = v.z; As[cq*4+3][r] = v.w;
        }
#pragma unroll
        for (int u = 0; u < 2; u++) {
            int idx = tid + u * 256;
            int kk = idx >> 5, nq = idx & 31;
            *(float4*)&Bs[kk][nq*4] =
                *(const float4*)&Bmat[(size_t)(k0+kk)*N + n0 + nq*4];
        }
        __syncthreads();
#pragma unroll
        for (int kk = 0; kk < BK; kk++) {
            float a[8], bfr[8];
            *(float4*)&a[0]   = *(const float4*)&As[kk][ty*4];
            *(float4*)&a[4]   = *(const float4*)&As[kk][64 + ty*4];
            *(float4*)&bfr[0] = *(const float4*)&Bs[kk][tx*4];
            *(float4*)&bfr[4] = *(const float4*)&Bs[kk][64 + tx*4];
#pragma unroll
            for (int i = 0; i < 8; i++)
#pragma unroll
                for (int j = 0; j < 8; j++) acc[i][j] += a[i] * bfr[j];
        }
        __syncthreads();
    }
#pragma unroll
    for (int i = 0; i < 8; i++) {
        int m = m0 + ((i < 4) ? (ty*4 + i) : (64 + ty*4 + i - 4));
        float bv = bm[m];
        float4 x0 = *(const float4*)&xr[(size_t)m*N + n0 + tx*4];
        float4 x1 = *(const float4*)&xr[(size_t)m*N + n0 + 64 + tx*4];
        float4 v0 = make_float4(acc[i][0]+bv+x0.x, acc[i][1]+bv+x0.y,
                                acc[i][2]+bv+x0.z, acc[i][3]+bv+x0.w);
        float4 v1 = make_float4(acc[i][4]+bv+x1.x, acc[i][5]+bv+x1.y,
                                acc[i][6]+bv+x1.z, acc[i][7]+bv+x1.w);
        *(float4*)&O[(size_t)m*N + n0 + tx*4]      = v0;
        *(float4*)&O[(size_t)m*N + n0 + 64 + tx*4] = v1;
    }
}

// ============================================================================
extern "C" void kernel_launch(void* const* d_in, const int* in_sizes, int n_in,
                              void* d_out, int out_size)
{
    const float* x       = (const float*)d_in[0];
    const float* w_phi   = (const float*)d_in[1];
    const float* b_phi   = (const float*)d_in[2];
    const float* w_theta = (const float*)d_in[3];
    const float* b_theta = (const float*)d_in[4];
    const float* w_g     = (const float*)d_in[5];
    const float* b_g     = (const float*)d_in[6];
    const float* w_mask  = (const float*)d_in[7];
    const float* b_mask  = (const float*)d_in[8];
    float* out = (float*)d_out;

    proj_kernel  <<<dim3(HW/BN, 1,        BATCH*3), 256>>>(x, w_phi, b_phi,
                                                            w_theta, b_theta,
                                                            w_g, b_g);
    scores_kernel<<<dim3(NV/BN, NV/BM,    BATCH),   256>>>();
    reduce_kernel<<<dim3(NV/256, BATCH),            256>>>();
    outgemm_kernel<<<dim3(NV/BN, CCH/BM,  BATCH),   256>>>();
    mask_kernel  <<<dim3(HW/BN, CCH/BM,   BATCH),   256>>>(w_mask, b_mask, x, out);
}

// round 4
// speedup vs baseline: 1.2494x; 1.2494x over previous
#include <cuda_runtime.h>
#include <cuda_bf16.h>
#include <math.h>
#include <stdint.h>

#define BATCH 16
#define CCH   256
#define ICH   128
#define HW    4096
#define NV    2048

#define BM 128
#define BN 128
#define BK 16

#define KPAD 24   // smem k stride (elems) for mma tiles: 48B row stride, conflict-free

// ---------------- scratch (device globals; no allocation allowed) ----------
// split-bf16 operands (k' = half*128 + ic remap for theta/phi)
__device__ __align__(16) __nv_bfloat16 g_thT_hi[(size_t)BATCH * NV * CCH];
__device__ __align__(16) __nv_bfloat16 g_thT_lo[(size_t)BATCH * NV * CCH];
__device__ __align__(16) __nv_bfloat16 g_phT_hi[(size_t)BATCH * NV * CCH];
__device__ __align__(16) __nv_bfloat16 g_phT_lo[(size_t)BATCH * NV * CCH];
__device__ __align__(16) __nv_bfloat16 g_g_hi [(size_t)BATCH * CCH * NV];
__device__ __align__(16) __nv_bfloat16 g_g_lo [(size_t)BATCH * CCH * NV];
__device__ __align__(16) __nv_bfloat16 g_p_hi [(size_t)BATCH * NV * NV];
__device__ __align__(16) __nv_bfloat16 g_p_lo [(size_t)BATCH * NV * NV];
__device__ float g_s    [(size_t)BATCH * NV * NV];     // fp32 scores
__device__ float g_o    [(size_t)BATCH * ICH * HW];    // outgemm fp32 result
__device__ float g_cmax [BATCH * NV];
__device__ float g_cinv [BATCH * NV];

// ============================================================================
// Kernel 1: projections (fp32 FFMA GEMM, unchanged mainloop) + split-bf16
// epilogues.  pj 0=phi, 1=theta (transposed outputs), 2=g (direct).
// ============================================================================
union ProjSmem {
    struct { float As[BK][BM + 4]; float Bs[BK][BN]; } g;
    __nv_bfloat16 t[128][136];    // transpose staging (272B row stride, 16B aligned)
};

__device__ __forceinline__ uint32_t pack_bf2(float a, float b) {
    __nv_bfloat162 h = __floats2bfloat162_rn(a, b);
    return *(uint32_t*)&h;
}

__global__ __launch_bounds__(256) void proj_kernel(
    const float* __restrict__ x,
    const float* __restrict__ w0, const float* __restrict__ b0,
    const float* __restrict__ w1, const float* __restrict__ b1,
    const float* __restrict__ w2, const float* __restrict__ b2)
{
    const int z = blockIdx.z;
    const int batch = z / 3;
    const int pj = z - batch * 3;
    const float* W    = (pj == 0) ? w0 : (pj == 1) ? w1 : w2;
    const float* bias = (pj == 0) ? b0 : (pj == 1) ? b1 : b2;
    const float* Bmat = x + (size_t)batch * CCH * HW;

    const int K = CCH, N = HW;
    const int n0 = blockIdx.x * BN;

    __shared__ ProjSmem sm;

    const int tid = threadIdx.x;
    const int tx = tid & 15, ty = tid >> 4;

    float acc[8][8];
#pragma unroll
    for (int i = 0; i < 8; i++)
#pragma unroll
        for (int j = 0; j < 8; j++) acc[i][j] = 0.f;

    for (int k0 = 0; k0 < K; k0 += BK) {
#pragma unroll
        for (int u = 0; u < 2; u++) {
            int idx = tid + u * 256;
            int r = idx >> 2, cq = idx & 3;
            float4 v = *(const float4*)&W[r * K + k0 + cq * 4];
            sm.g.As[cq*4+0][r] = v.x; sm.g.As[cq*4+1][r] = v.y;
            sm.g.As[cq*4+2][r] = v.z; sm.g.As[cq*4+3][r] = v.w;
        }
#pragma unroll
        for (int u = 0; u < 2; u++) {
            int idx = tid + u * 256;
            int kk = idx >> 5, nq = idx & 31;
            *(float4*)&sm.g.Bs[kk][nq*4] =
                *(const float4*)&Bmat[(size_t)(k0+kk)*N + n0 + nq*4];
        }
        __syncthreads();
#pragma unroll
        for (int kk = 0; kk < BK; kk++) {
            float a[8], b[8];
            *(float4*)&a[0] = *(const float4*)&sm.g.As[kk][ty*4];
            *(float4*)&a[4] = *(const float4*)&sm.g.As[kk][64 + ty*4];
            *(float4*)&b[0] = *(const float4*)&sm.g.Bs[kk][tx*4];
            *(float4*)&b[4] = *(const float4*)&sm.g.Bs[kk][64 + tx*4];
#pragma unroll
            for (int i = 0; i < 8; i++)
#pragma unroll
                for (int j = 0; j < 8; j++) acc[i][j] += a[i] * b[j];
        }
        __syncthreads();
    }

    // add bias
#pragma unroll
    for (int i = 0; i < 8; i++) {
        int m = (i < 4) ? (ty*4 + i) : (64 + ty*4 + i - 4);
        float bv = bias[m];
#pragma unroll
        for (int j = 0; j < 8; j++) acc[i][j] += bv;
    }

    const int half = n0 / 2048;          // which half of hw
    const int nr0  = n0 - half * 2048;   // local col base in [0,2048)

    if (pj == 2) {
        // g: direct split write.  row c = 2*ic + half, col m = hw%2048
        __nv_bfloat16* gh = g_g_hi + (size_t)batch * CCH * NV;
        __nv_bfloat16* gl = g_g_lo + (size_t)batch * CCH * NV;
#pragma unroll
        for (int i = 0; i < 8; i++) {
            int ic = (i < 4) ? (ty*4 + i) : (64 + ty*4 + i - 4);
            int c = 2*ic + half;
#pragma unroll
            for (int jg = 0; jg < 2; jg++) {        // two 4-col groups
                int colb = nr0 + jg*64 + tx*4;
                float v0 = acc[i][jg*4+0], v1 = acc[i][jg*4+1];
                float v2 = acc[i][jg*4+2], v3 = acc[i][jg*4+3];
                __nv_bfloat16 h0 = __float2bfloat16(v0), h1 = __float2bfloat16(v1);
                __nv_bfloat16 h2 = __float2bfloat16(v2), h3 = __float2bfloat16(v3);
                uint2 hv, lv;
                hv.x = pack_bf2(v0, v1) * 0 + ((uint32_t)*(uint16_t*)&h0 | ((uint32_t)*(uint16_t*)&h1 << 16));
                hv.y = ((uint32_t)*(uint16_t*)&h2 | ((uint32_t)*(uint16_t*)&h3 << 16));
                lv.x = pack_bf2(v0 - __bfloat162float(h0), v1 - __bfloat162float(h1));
                lv.y = pack_bf2(v2 - __bfloat162float(h2), v3 - __bfloat162float(h3));
                *(uint2*)&gh[(size_t)c*NV + colb] = hv;
                *(uint2*)&gl[(size_t)c*NV + colb] = lv;
            }
        }
    } else {
        // phi/theta: transpose through smem, write T[n][k'=half*128+ic]
        __nv_bfloat16* Thi = ((pj == 0) ? g_phT_hi : g_thT_hi) + (size_t)batch * NV * CCH;
        __nv_bfloat16* Tlo = ((pj == 0) ? g_phT_lo : g_thT_lo) + (size_t)batch * NV * CCH;

        for (int pass = 0; pass < 2; pass++) {
#pragma unroll
            for (int i = 0; i < 8; i++) {
                int m = (i < 4) ? (ty*4 + i) : (64 + ty*4 + i - 4);
#pragma unroll
                for (int j = 0; j < 8; j++) {
                    int col = (j < 4) ? (tx*4 + j) : (64 + tx*4 + j - 4);
                    float v = acc[i][j];
                    __nv_bfloat16 h = __float2bfloat16(v);
                    sm.t[col][m] = (pass == 0) ? h
                                 : __float2bfloat16(v - __bfloat162float(h));
                }
            }
            __syncthreads();
            {
                int row = tid >> 1, seg = tid & 1;
                __nv_bfloat16* dstb = (pass == 0 ? Thi : Tlo)
                    + (size_t)(nr0 + row) * CCH + half*128 + seg*64;
                const uint4* src = (const uint4*)&sm.t[row][seg*64];
                uint4* dst = (uint4*)dstb;
#pragma unroll
                for (int q = 0; q < 8; q++) dst[q] = src[q];
            }
            __syncthreads();
        }
    }
}

// ============================================================================
// Split-bf16 tensor-core GEMM:  C[row][col] = sum_k A[row][k]*B[col][k]
// A = Ahi+Alo, B = Bhi+Blo (3-term).  Block 128x128, warp 64x32, 2-stage
// cp.async pipeline, BK=16 per stage.  lda = ldb = K, ldc = NV.
// ============================================================================
__device__ __forceinline__ void mma_bf16(float* d, const uint32_t* a, const uint32_t* b) {
    asm volatile(
        "mma.sync.aligned.m16n8k16.row.col.f32.bf16.bf16.f32 "
        "{%0,%1,%2,%3}, {%4,%5,%6,%7}, {%8,%9}, {%0,%1,%2,%3};"
        : "+f"(d[0]), "+f"(d[1]), "+f"(d[2]), "+f"(d[3])
        : "r"(a[0]), "r"(a[1]), "r"(a[2]), "r"(a[3]), "r"(b[0]), "r"(b[1]));
}

__device__ __forceinline__ void cp_async16(uint32_t saddr, const void* gptr) {
    asm volatile("cp.async.cg.shared.global [%0], [%1], 16;\n" :: "r"(saddr), "l"(gptr));
}

__global__ __launch_bounds__(256, 1) void mma_gemm_kernel(
    const __nv_bfloat16* __restrict__ Ahi, const __nv_bfloat16* __restrict__ Alo,
    const __nv_bfloat16* __restrict__ Bhi, const __nv_bfloat16* __restrict__ Blo,
    float* __restrict__ C, int K,
    size_t strideA, size_t strideB, size_t strideC)
{
    __shared__ __nv_bfloat16 SA[2][2][128][KPAD];   // [stage][hi/lo][row][k]
    __shared__ __nv_bfloat16 SB[2][2][128][KPAD];

    const int b  = blockIdx.z;
    const int m0 = blockIdx.y * 128;
    const int n0 = blockIdx.x * 128;
    const int tid  = threadIdx.x;
    const int lane = tid & 31;
    const int w    = tid >> 5;
    const int m_base = (w & 1) * 64;
    const int n_base = (w >> 1) * 32;
    const int r  = lane >> 2;
    const int c2 = (lane & 3) * 2;

    const __nv_bfloat16* Ah = Ahi + (size_t)b * strideA;
    const __nv_bfloat16* Al = Alo + (size_t)b * strideA;
    const __nv_bfloat16* Bh = Bhi + (size_t)b * strideB;
    const __nv_bfloat16* Bl = Blo + (size_t)b * strideB;
    float* Cb = C + (size_t)b * strideC;

    const int lrow = tid >> 1, lhalf = tid & 1;   // loader mapping: 16B per array
    const int S = K / 16;

    float acc[4][4][4];
#pragma unroll
    for (int i = 0; i < 4; i++)
#pragma unroll
        for (int j = 0; j < 4; j++)
#pragma unroll
            for (int q = 0; q < 4; q++) acc[i][j][q] = 0.f;

    auto load_stage = [&](int st, int ks) {
        size_t ga = (size_t)(m0 + lrow) * K + ks * 16 + lhalf * 8;
        size_t gb = (size_t)(n0 + lrow) * K + ks * 16 + lhalf * 8;
        cp_async16((uint32_t)__cvta_generic_to_shared(&SA[st][0][lrow][lhalf*8]), Ah + ga);
        cp_async16((uint32_t)__cvta_generic_to_shared(&SA[st][1][lrow][lhalf*8]), Al + ga);
        cp_async16((uint32_t)__cvta_generic_to_shared(&SB[st][0][lrow][lhalf*8]), Bh + gb);
        cp_async16((uint32_t)__cvta_generic_to_shared(&SB[st][1][lrow][lhalf*8]), Bl + gb);
    };

    load_stage(0, 0);
    asm volatile("cp.async.commit_group;\n");

    for (int s = 0; s < S; s++) {
        int st = s & 1;
        if (s + 1 < S) {
            load_stage(st ^ 1, s + 1);
            asm volatile("cp.async.commit_group;\n");
            asm volatile("cp.async.wait_group 1;\n");
        } else {
            asm volatile("cp.async.wait_group 0;\n");
        }
        __syncthreads();

        uint32_t ah[4][4], al[4][4], bh[4][2], bl[4][2];
#pragma unroll
        for (int i = 0; i < 4; i++) {
            int r0 = m_base + i * 16 + r;
            ah[i][0] = *(const uint32_t*)&SA[st][0][r0    ][c2];
            ah[i][1] = *(const uint32_t*)&SA[st][0][r0 + 8][c2];
            ah[i][2] = *(const uint32_t*)&SA[st][0][r0    ][c2 + 8];
            ah[i][3] = *(const uint32_t*)&SA[st][0][r0 + 8][c2 + 8];
            al[i][0] = *(const uint32_t*)&SA[st][1][r0    ][c2];
            al[i][1] = *(const uint32_t*)&SA[st][1][r0 + 8][c2];
            al[i][2] = *(const uint32_t*)&SA[st][1][r0    ][c2 + 8];
            al[i][3] = *(const uint32_t*)&SA[st][1][r0 + 8][c2 + 8];
        }
#pragma unroll
        for (int j = 0; j < 4; j++) {
            int nr = n_base + j * 8 + r;
            bh[j][0] = *(const uint32_t*)&SB[st][0][nr][c2];
            bh[j][1] = *(const uint32_t*)&SB[st][0][nr][c2 + 8];
            bl[j][0] = *(const uint32_t*)&SB[st][1][nr][c2];
            bl[j][1] = *(const uint32_t*)&SB[st][1][nr][c2 + 8];
        }
#pragma unroll
        for (int i = 0; i < 4; i++)
#pragma unroll
            for (int j = 0; j < 4; j++) {
                mma_bf16(acc[i][j], ah[i], bh[j]);   // hi*hi
                mma_bf16(acc[i][j], ah[i], bl[j]);   // hi*lo
                mma_bf16(acc[i][j], al[i], bh[j]);   // lo*hi
            }
        __syncthreads();
    }

    // epilogue
#pragma unroll
    for (int i = 0; i < 4; i++) {
        int row = m0 + m_base + i * 16 + r;
#pragma unroll
        for (int j = 0; j < 4; j++) {
            int col = n0 + n_base + j * 8 + c2;
            *(float2*)&Cb[(size_t)row * NV + col] =
                make_float2(acc[i][j][0], acc[i][j][1]);
            *(float2*)&Cb[(size_t)(row + 8) * NV + col] =
                make_float2(acc[i][j][2], acc[i][j][3]);
        }
    }
}

// ============================================================================
// Kernel 3: per-column (m) online softmax stats over rows n.
// ============================================================================
__global__ __launch_bounds__(256) void reduce_kernel()
{
    const int b = blockIdx.y;
    const int m = blockIdx.x * 256 + threadIdx.x;
    const float* S = g_s + (size_t)b * NV * NV;

    float mx = __int_as_float(0xff800000);
    float sm = 0.f;
    for (int n = 0; n < NV; n += 8) {
        float v[8];
#pragma unroll
        for (int q = 0; q < 8; q++) v[q] = S[(size_t)(n+q)*NV + m];
#pragma unroll
        for (int q = 0; q < 8; q++) {
            float nm = fmaxf(mx, v[q]);
            sm = sm * expf(mx - nm) + expf(v[q] - nm);
            mx = nm;
        }
    }
    g_cmax[b*NV + m] = mx;
    g_cinv[b*NV + m] = 1.0f / sm;
}

// ============================================================================
// Kernel 4: P-pass.  P[n][m] = exp(S[n][m]-cmax[m]) * cinv[m], split bf16.
// ============================================================================
__global__ __launch_bounds__(256) void ppass_kernel()
{
    const int b = blockIdx.y;
    const size_t base = ((size_t)blockIdx.x * 256 + threadIdx.x) * 4;
    const int m = (int)(base & (NV - 1));

    float4 s  = *(const float4*)&g_s[(size_t)b * NV * NV + base];
    float4 cm = *(const float4*)&g_cmax[b * NV + m];
    float4 ci = *(const float4*)&g_cinv[b * NV + m];

    float p0 = expf(s.x - cm.x) * ci.x;
    float p1 = expf(s.y - cm.y) * ci.y;
    float p2 = expf(s.z - cm.z) * ci.z;
    float p3 = expf(s.w - cm.w) * ci.w;

    __nv_bfloat16 h0 = __float2bfloat16(p0), h1 = __float2bfloat16(p1);
    __nv_bfloat16 h2 = __float2bfloat16(p2), h3 = __float2bfloat16(p3);
    uint2 hv, lv;
    hv.x = ((uint32_t)*(uint16_t*)&h0 | ((uint32_t)*(uint16_t*)&h1 << 16));
    hv.y = ((uint32_t)*(uint16_t*)&h2 | ((uint32_t)*(uint16_t*)&h3 << 16));
    lv.x = pack_bf2(p0 - __bfloat162float(h0), p1 - __bfloat162float(h1));
    lv.y = pack_bf2(p2 - __bfloat162float(h2), p3 - __bfloat162float(h3));
    *(uint2*)&g_p_hi[(size_t)b * NV * NV + base] = hv;
    *(uint2*)&g_p_lo[(size_t)b * NV * NV + base] = lv;
}

// ============================================================================
// Kernel 6: mask conv + bias + residual (fp32 SIMT, reads g_o).
// ============================================================================
__global__ __launch_bounds__(256) void mask_kernel(
    const float* __restrict__ wm, const float* __restrict__ bm,
    const float* __restrict__ x, float* __restrict__ outp)
{
    const int b = blockIdx.z;
    const float* Bmat = g_o + (size_t)b * ICH * HW;
    const float* xr   = x   + (size_t)b * CCH * HW;
    float* O          = outp + (size_t)b * CCH * HW;

    const int K = ICH, N = HW;
    const int m0 = blockIdx.y * BM;
    const int n0 = blockIdx.x * BN;

    __shared__ __align__(16) float As[BK][BM + 4];
    __shared__ __align__(16) float Bs[BK][BN];

    const int tid = threadIdx.x;
    const int tx = tid & 15, ty = tid >> 4;

    float acc[8][8];
#pragma unroll
    for (int i = 0; i < 8; i++)
#pragma unroll
        for (int j = 0; j < 8; j++) acc[i][j] = 0.f;

    for (int k0 = 0; k0 < K; k0 += BK) {
#pragma unroll
        for (int u = 0; u < 2; u++) {
            int idx = tid + u * 256;
            int rr = idx >> 2, cq = idx & 3;
            float4 v = *(const float4*)&wm[(size_t)(m0+rr)*K + k0 + cq*4];
            As[cq*4+0][rr] = v.x; As[cq*4+1][rr] = v.y;
            As[cq*4+2][rr] = v.z; As[cq*4+3][rr] = v.w;
        }
#pragma unroll
        for (int u = 0; u < 2; u++) {
            int idx = tid + u * 256;
            int kk = idx >> 5, nq = idx & 31;
            *(float4*)&Bs[kk][nq*4] =
                *(const float4*)&Bmat[(size_t)(k0+kk)*N + n0 + nq*4];
        }
        __syncthreads();
#pragma unroll
        for (int kk = 0; kk < BK; kk++) {
            float a[8], bfr[8];
            *(float4*)&a[0]   = *(const float4*)&As[kk][ty*4];
            *(float4*)&a[4]   = *(const float4*)&As[kk][64 + ty*4];
            *(float4*)&bfr[0] = *(const float4*)&Bs[kk][tx*4];
            *(float4*)&bfr[4] = *(const float4*)&Bs[kk][64 + tx*4];
#pragma unroll
            for (int i = 0; i < 8; i++)
#pragma unroll
                for (int j = 0; j < 8; j++) acc[i][j] += a[i] * bfr[j];
        }
        __syncthreads();
    }
#pragma unroll
    for (int i = 0; i < 8; i++) {
        int m = m0 + ((i < 4) ? (ty*4 + i) : (64 + ty*4 + i - 4));
        float bv = bm[m];
        float4 x0 = *(const float4*)&xr[(size_t)m*N + n0 + tx*4];
        float4 x1 = *(const float4*)&xr[(size_t)m*N + n0 + 64 + tx*4];
        float4 v0 = make_float4(acc[i][0]+bv+x0.x, acc[i][1]+bv+x0.y,
                                acc[i][2]+bv+x0.z, acc[i][3]+bv+x0.w);
        float4 v1 = make_float4(acc[i][4]+bv+x1.x, acc[i][5]+bv+x1.y,
                                acc[i][6]+bv+x1.z, acc[i][7]+bv+x1.w);
        *(float4*)&O[(size_t)m*N + n0 + tx*4]      = v0;
        *(float4*)&O[(size_t)m*N + n0 + 64 + tx*4] = v1;
    }
}

// ============================================================================
extern "C" void kernel_launch(void* const* d_in, const int* in_sizes, int n_in,
                              void* d_out, int out_size)
{
    const float* x       = (const float*)d_in[0];
    const float* w_phi   = (const float*)d_in[1];
    const float* b_phi   = (const float*)d_in[2];
    const float* w_theta = (const float*)d_in[3];
    const float* b_theta = (const float*)d_in[4];
    const float* w_g     = (const float*)d_in[5];
    const float* b_g     = (const float*)d_in[6];
    const float* w_mask  = (const float*)d_in[7];
    const float* b_mask  = (const float*)d_in[8];
    float* out = (float*)d_out;

    __nv_bfloat16 *thT_hi, *thT_lo, *phT_hi, *phT_lo, *ghi, *glo, *phi_p, *plo_p;
    float *sptr, *optr;
    cudaGetSymbolAddress((void**)&thT_hi, g_thT_hi);
    cudaGetSymbolAddress((void**)&thT_lo, g_thT_lo);
    cudaGetSymbolAddress((void**)&phT_hi, g_phT_hi);
    cudaGetSymbolAddress((void**)&phT_lo, g_phT_lo);
    cudaGetSymbolAddress((void**)&ghi,    g_g_hi);
    cudaGetSymbolAddress((void**)&glo,    g_g_lo);
    cudaGetSymbolAddress((void**)&phi_p,  g_p_hi);
    cudaGetSymbolAddress((void**)&plo_p,  g_p_lo);
    cudaGetSymbolAddress((void**)&sptr,   g_s);
    cudaGetSymbolAddress((void**)&optr,   g_o);

    // 1) projections -> split-bf16 operands
    proj_kernel<<<dim3(HW/BN, 1, BATCH*3), 256>>>(x, w_phi, b_phi,
                                                   w_theta, b_theta, w_g, b_g);
    // 2) scores: S[n][m] = theta^T . phi   (M=N=2048, K=256)
    mma_gemm_kernel<<<dim3(16, 16, BATCH), 256>>>(
        thT_hi, thT_lo, phT_hi, phT_lo, sptr, CCH,
        (size_t)NV*CCH, (size_t)NV*CCH, (size_t)NV*NV);
    // 3) column softmax stats
    reduce_kernel<<<dim3(NV/256, BATCH), 256>>>();
    // 4) P = exp(S - cmax)*cinv, split bf16
    ppass_kernel<<<dim3((NV*NV)/(256*4), BATCH), 256>>>();
    // 5) out: O[c][n] = g . P^T   (M=256, N=2048, K=2048)
    mma_gemm_kernel<<<dim3(16, 2, BATCH), 256>>>(
        ghi, glo, phi_p, plo_p, optr, NV,
        (size_t)CCH*NV, (size_t)NV*NV, (size_t)ICH*HW);
    // 6) mask conv + residual
    mask_kernel<<<dim3(HW/BN, CCH/BM, BATCH), 256>>>(w_mask, b_mask, x, out);
}

// round 7
// speedup vs baseline: 1.2863x; 1.0295x over previous
#include <cuda_runtime.h>
#include <cuda_bf16.h>
#include <math.h>
#include <stdint.h>

#define BATCH 16
#define CCH   256
#define ICH   128
#define HW    4096
#define NV    2048

#define BM 128
#define BN 128
#define BK 16

// ---------------- scratch (device globals; no allocation allowed) ----------
__device__ __align__(16) __nv_bfloat16 g_thT_hi[(size_t)BATCH * NV * CCH];
__device__ __align__(16) __nv_bfloat16 g_thT_lo[(size_t)BATCH * NV * CCH];
__device__ __align__(16) __nv_bfloat16 g_phT_hi[(size_t)BATCH * NV * CCH];
__device__ __align__(16) __nv_bfloat16 g_phT_lo[(size_t)BATCH * NV * CCH];
__device__ __align__(16) __nv_bfloat16 g_g_hi [(size_t)BATCH * CCH * NV];
__device__ __align__(16) __nv_bfloat16 g_g_lo [(size_t)BATCH * CCH * NV];
__device__ __align__(16) __nv_bfloat16 g_p_hi [(size_t)BATCH * NV * NV];
__device__ __align__(16) __nv_bfloat16 g_p_lo [(size_t)BATCH * NV * NV];
__device__ float g_s    [(size_t)BATCH * NV * NV];
__device__ float g_o    [(size_t)BATCH * ICH * HW];
__device__ float g_cmax [BATCH * NV];
__device__ float g_cinv [BATCH * NV];

// ---------------- helpers ---------------------------------------------------
#define SWZ(x) ((x) ^ (((x) >> 3) & 0x70))   // 128B-row swizzle

__device__ __forceinline__ uint32_t smem_to_u32(const void* p) {
    uint32_t a;
    asm("{ .reg .u64 t; cvta.to.shared.u64 t, %1; cvt.u32.u64 %0, t; }"
        : "=r"(a) : "l"(p));
    return a;
}
__device__ __forceinline__ void mma_bf16(float* d, const uint32_t* a, const uint32_t* b) {
    asm volatile(
        "mma.sync.aligned.m16n8k16.row.col.f32.bf16.bf16.f32 "
        "{%0,%1,%2,%3}, {%4,%5,%6,%7}, {%8,%9}, {%0,%1,%2,%3};"
        : "+f"(d[0]), "+f"(d[1]), "+f"(d[2]), "+f"(d[3])
        : "r"(a[0]), "r"(a[1]), "r"(a[2]), "r"(a[3]), "r"(b[0]), "r"(b[1]));
}
__device__ __forceinline__ void ldm_x4(uint32_t* r, uint32_t addr) {
    asm volatile("ldmatrix.sync.aligned.m8n8.x4.shared.b16 {%0,%1,%2,%3}, [%4];"
                 : "=r"(r[0]), "=r"(r[1]), "=r"(r[2]), "=r"(r[3]) : "r"(addr));
}
__device__ __forceinline__ void cp_async16(uint32_t saddr, const void* gptr) {
    asm volatile("cp.async.cg.shared.global [%0], [%1], 16;\n" :: "r"(saddr), "l"(gptr));
}
__device__ __forceinline__ uint32_t pack_bf2(float a, float b) {
    __nv_bfloat162 h = __floats2bfloat162_rn(a, b);
    return *(uint32_t*)&h;
}

// ============================================================================
// Split-bf16 mma.sync GEMM:  C[r][c] = sum_k A[r][k]*B[c][k]  (3-term).
// Block 128x128, warp 64x32, 3-stage cp.async pipeline, K-stage 32.
// smem per stage: A-rows and B-rows of 128B = [hi 64B | lo 64B], SW128 swizzle.
// 32KB/stage * 3 = 96KB dynamic smem -> 2 CTAs/SM with <=128 regs.
// ============================================================================
#define TCG_SMEM_BYTES (3 * 32768)

__global__ __launch_bounds__(256, 2) void mma_gemm_kernel(
    const __nv_bfloat16* __restrict__ Ahi, const __nv_bfloat16* __restrict__ Alo,
    const __nv_bfloat16* __restrict__ Bhi, const __nv_bfloat16* __restrict__ Blo,
    float* __restrict__ C, int K,
    size_t strideA, size_t strideB, size_t strideC)
{
    extern __shared__ __align__(128) uint8_t smem[];
    const uint32_t s0 = smem_to_u32(smem);

    const int b  = blockIdx.z;
    const int m0 = blockIdx.y * 128;
    const int n0 = blockIdx.x * 128;
    const int tid  = threadIdx.x;
    const int lane = tid & 31;
    const int w    = tid >> 5;
    const int m_base = (w & 1) * 64;
    const int n_base = (w >> 1) * 32;
    const int r  = lane >> 2;
    const int c2 = (lane & 3) * 2;

    const __nv_bfloat16* Ah = Ahi + (size_t)b * strideA;
    const __nv_bfloat16* Al = Alo + (size_t)b * strideA;
    const __nv_bfloat16* Bh = Bhi + (size_t)b * strideB;
    const __nv_bfloat16* Bl = Blo + (size_t)b * strideB;
    float* Cb = C + (size_t)b * strideC;

    const int S = K / 32;
    const int lrow = tid >> 1;           // loader: 2 threads per row, 4 chunks each
    const int lquad = tid & 1;

    float acc[4][4][4];
#pragma unroll
    for (int i = 0; i < 4; i++)
#pragma unroll
        for (int j = 0; j < 4; j++)
#pragma unroll
            for (int q = 0; q < 4; q++) acc[i][j][q] = 0.f;

    // per-stage loader: A buf at +0, B buf at +16384 within the 32KB stage.
    auto load_stage = [&](int s) {
        const uint32_t sb = s0 + (s % 3) * 32768;
        const int k0 = s * 32;
#pragma unroll
        for (int u4 = 0; u4 < 4; u4++) {
            int u = lquad * 4 + u4;      // chunk 0..7 within 128B row
            uint32_t dsw = SWZ((uint32_t)(lrow * 128 + u * 16));
            const __nv_bfloat16* srcA = (u < 4) ? Ah : Al;
            const __nv_bfloat16* srcB = (u < 4) ? Bh : Bl;
            int ke = k0 + (u & 3) * 8;
            cp_async16(sb + dsw,         srcA + (size_t)(m0 + lrow) * K + ke);
            cp_async16(sb + 16384 + dsw, srcB + (size_t)(n0 + lrow) * K + ke);
        }
        asm volatile("cp.async.commit_group;\n");
    };

    load_stage(0);
    load_stage(1);

    const int jj   = lane >> 4;          // 0/1: second half of x4
    const int sub  = (lane >> 3) & 1;    // k-half within x4 for B
    const int l7   = lane & 7;
    const int l15  = lane & 15;

    for (int s = 0; s < S; s++) {
        if (s + 1 < S) asm volatile("cp.async.wait_group 1;\n");
        else           asm volatile("cp.async.wait_group 0;\n");
        __syncthreads();

        const uint32_t SAb = s0 + (s % 3) * 32768;
        const uint32_t SBb = SAb + 16384;

#pragma unroll
        for (int kk16 = 0; kk16 < 32; kk16 += 16) {
            uint32_t bh[4][2], bl[4][2];
#pragma unroll
            for (int jp = 0; jp < 2; jp++) {
                int row = n_base + (jp * 2 + jj) * 8 + l7;
                uint32_t off = (uint32_t)(row * 128 + (kk16 + sub * 8) * 2);
                uint32_t r4[4];
                ldm_x4(r4, SBb + SWZ(off));
                bh[jp*2][0] = r4[0]; bh[jp*2][1] = r4[1];
                bh[jp*2+1][0] = r4[2]; bh[jp*2+1][1] = r4[3];
                ldm_x4(r4, SBb + SWZ(off + 64));
                bl[jp*2][0] = r4[0]; bl[jp*2][1] = r4[1];
                bl[jp*2+1][0] = r4[2]; bl[jp*2+1][1] = r4[3];
            }
#pragma unroll
            for (int i = 0; i < 4; i++) {
                int row = m_base + i * 16 + l15;
                uint32_t off = (uint32_t)(row * 128 + (kk16 + jj * 8) * 2);
                uint32_t ah[4], al[4];
                ldm_x4(ah, SAb + SWZ(off));
                ldm_x4(al, SAb + SWZ(off + 64));
#pragma unroll
                for (int j = 0; j < 4; j++) {
                    mma_bf16(acc[i][j], ah, bh[j]);
                    mma_bf16(acc[i][j], ah, bl[j]);
                    mma_bf16(acc[i][j], al, bh[j]);
                }
            }
        }
        __syncthreads();
        if (s + 2 < S) load_stage(s + 2);
    }

    // epilogue: direct fragment stores (32B segments, sector-aligned)
#pragma unroll
    for (int i = 0; i < 4; i++) {
        int row = m0 + m_base + i * 16 + r;
#pragma unroll
        for (int j = 0; j < 4; j++) {
            int col = n0 + n_base + j * 8 + c2;
            *(float2*)&Cb[(size_t)row * NV + col] =
                make_float2(acc[i][j][0], acc[i][j][1]);
            *(float2*)&Cb[(size_t)(row + 8) * NV + col] =
                make_float2(acc[i][j][2], acc[i][j][3]);
        }
    }
}

// ============================================================================
// Kernel 1: projections (fp32 FFMA GEMM) + split-bf16 epilogues.
// ============================================================================
union ProjSmem {
    struct { float As[BK][BM + 4]; float Bs[BK][BN]; } g;
    __nv_bfloat16 t[128][136];
};

__global__ __launch_bounds__(256) void proj_kernel(
    const float* __restrict__ x,
    const float* __restrict__ w0, const float* __restrict__ b0,
    const float* __restrict__ w1, const float* __restrict__ b1,
    const float* __restrict__ w2, const float* __restrict__ b2)
{
    const int z = blockIdx.z;
    const int batch = z / 3;
    const int pj = z - batch * 3;
    const float* W    = (pj == 0) ? w0 : (pj == 1) ? w1 : w2;
    const float* bias = (pj == 0) ? b0 : (pj == 1) ? b1 : b2;
    const float* Bmat = x + (size_t)batch * CCH * HW;

    const int K = CCH, N = HW;
    const int n0 = blockIdx.x * BN;

    __shared__ ProjSmem sm;

    const int tid = threadIdx.x;
    const int tx = tid & 15, ty = tid >> 4;

    float acc[8][8];
#pragma unroll
    for (int i = 0; i < 8; i++)
#pragma unroll
        for (int j = 0; j < 8; j++) acc[i][j] = 0.f;

    for (int k0 = 0; k0 < K; k0 += BK) {
#pragma unroll
        for (int u = 0; u < 2; u++) {
            int idx = tid + u * 256;
            int rr = idx >> 2, cq = idx & 3;
            float4 v = *(const float4*)&W[rr * K + k0 + cq * 4];
            sm.g.As[cq*4+0][rr] = v.x; sm.g.As[cq*4+1][rr] = v.y;
            sm.g.As[cq*4+2][rr] = v.z; sm.g.As[cq*4+3][rr] = v.w;
        }
#pragma unroll
        for (int u = 0; u < 2; u++) {
            int idx = tid + u * 256;
            int kk = idx >> 5, nq = idx & 31;
            *(float4*)&sm.g.Bs[kk][nq*4] =
                *(const float4*)&Bmat[(size_t)(k0+kk)*N + n0 + nq*4];
        }
        __syncthreads();
#pragma unroll
        for (int kk = 0; kk < BK; kk++) {
            float a[8], bb[8];
            *(float4*)&a[0] = *(const float4*)&sm.g.As[kk][ty*4];
            *(float4*)&a[4] = *(const float4*)&sm.g.As[kk][64 + ty*4];
            *(float4*)&bb[0] = *(const float4*)&sm.g.Bs[kk][tx*4];
            *(float4*)&bb[4] = *(const float4*)&sm.g.Bs[kk][64 + tx*4];
#pragma unroll
            for (int i = 0; i < 8; i++)
#pragma unroll
                for (int j = 0; j < 8; j++) acc[i][j] += a[i] * bb[j];
        }
        __syncthreads();
    }

#pragma unroll
    for (int i = 0; i < 8; i++) {
        int m = (i < 4) ? (ty*4 + i) : (64 + ty*4 + i - 4);
        float bv = bias[m];
#pragma unroll
        for (int j = 0; j < 8; j++) acc[i][j] += bv;
    }

    const int half = n0 / 2048;
    const int nr0  = n0 - half * 2048;

    if (pj == 2) {
        __nv_bfloat16* gh = g_g_hi + (size_t)batch * CCH * NV;
        __nv_bfloat16* gl = g_g_lo + (size_t)batch * CCH * NV;
#pragma unroll
        for (int i = 0; i < 8; i++) {
            int ic = (i < 4) ? (ty*4 + i) : (64 + ty*4 + i - 4);
            int c = 2*ic + half;
#pragma unroll
            for (int jg = 0; jg < 2; jg++) {
                int colb = nr0 + jg*64 + tx*4;
                float v0 = acc[i][jg*4+0], v1 = acc[i][jg*4+1];
                float v2 = acc[i][jg*4+2], v3 = acc[i][jg*4+3];
                __nv_bfloat16 h0 = __float2bfloat16(v0), h1 = __float2bfloat16(v1);
                __nv_bfloat16 h2 = __float2bfloat16(v2), h3 = __float2bfloat16(v3);
                uint2 hv, lv;
                hv.x = ((uint32_t)*(uint16_t*)&h0 | ((uint32_t)*(uint16_t*)&h1 << 16));
                hv.y = ((uint32_t)*(uint16_t*)&h2 | ((uint32_t)*(uint16_t*)&h3 << 16));
                lv.x = pack_bf2(v0 - __bfloat162float(h0), v1 - __bfloat162float(h1));
                lv.y = pack_bf2(v2 - __bfloat162float(h2), v3 - __bfloat162float(h3));
                *(uint2*)&gh[(size_t)c*NV + colb] = hv;
                *(uint2*)&gl[(size_t)c*NV + colb] = lv;
            }
        }
    } else {
        __nv_bfloat16* Thi = ((pj == 0) ? g_phT_hi : g_thT_hi) + (size_t)batch * NV * CCH;
        __nv_bfloat16* Tlo = ((pj == 0) ? g_phT_lo : g_thT_lo) + (size_t)batch * NV * CCH;

        for (int pass = 0; pass < 2; pass++) {
#pragma unroll
            for (int i = 0; i < 8; i++) {
                int m = (i < 4) ? (ty*4 + i) : (64 + ty*4 + i - 4);
#pragma unroll
                for (int j = 0; j < 8; j++) {
                    int col = (j < 4) ? (tx*4 + j) : (64 + tx*4 + j - 4);
                    float v = acc[i][j];
                    __nv_bfloat16 h = __float2bfloat16(v);
                    sm.t[col][m] = (pass == 0) ? h
                                 : __float2bfloat16(v - __bfloat162float(h));
                }
            }
            __syncthreads();
            {
                int row = tid >> 1, seg = tid & 1;
                __nv_bfloat16* dstb = (pass == 0 ? Thi : Tlo)
                    + (size_t)(nr0 + row) * CCH + half*128 + seg*64;
                const uint4* src = (const uint4*)&sm.t[row][seg*64];
                uint4* dst = (uint4*)dstb;
#pragma unroll
                for (int q = 0; q < 8; q++) dst[q] = src[q];
            }
            __syncthreads();
        }
    }
}

// ============================================================================
// Kernel 3: per-column (m) online softmax stats over rows n.
// ============================================================================
__global__ __launch_bounds__(256) void reduce_kernel()
{
    const int b = blockIdx.y;
    const int m = blockIdx.x * 256 + threadIdx.x;
    const float* S = g_s + (size_t)b * NV * NV;

    float mx = __int_as_float(0xff800000);
    float sm = 0.f;
    for (int n = 0; n < NV; n += 8) {
        float v[8];
#pragma unroll
        for (int q = 0; q < 8; q++) v[q] = S[(size_t)(n+q)*NV + m];
#pragma unroll
        for (int q = 0; q < 8; q++) {
            float nm = fmaxf(mx, v[q]);
            sm = sm * expf(mx - nm) + expf(v[q] - nm);
            mx = nm;
        }
    }
    g_cmax[b*NV + m] = mx;
    g_cinv[b*NV + m] = 1.0f / sm;
}

// ============================================================================
// Kernel 4: P-pass.  P[n][m] = exp(S[n][m]-cmax[m]) * cinv[m], split bf16.
// ============================================================================
__global__ __launch_bounds__(256) void ppass_kernel()
{
    const int b = blockIdx.y;
    const size_t base = ((size_t)blockIdx.x * 256 + threadIdx.x) * 4;
    const int m = (int)(base & (NV - 1));

    float4 s  = *(const float4*)&g_s[(size_t)b * NV * NV + base];
    float4 cm = *(const float4*)&g_cmax[b * NV + m];
    float4 ci = *(const float4*)&g_cinv[b * NV + m];

    float p0 = expf(s.x - cm.x) * ci.x;
    float p1 = expf(s.y - cm.y) * ci.y;
    float p2 = expf(s.z - cm.z) * ci.z;
    float p3 = expf(s.w - cm.w) * ci.w;

    __nv_bfloat16 h0 = __float2bfloat16(p0), h1 = __float2bfloat16(p1);
    __nv_bfloat16 h2 = __float2bfloat16(p2), h3 = __float2bfloat16(p3);
    uint2 hv, lv;
    hv.x = ((uint32_t)*(uint16_t*)&h0 | ((uint32_t)*(uint16_t*)&h1 << 16));
    hv.y = ((uint32_t)*(uint16_t*)&h2 | ((uint32_t)*(uint16_t*)&h3 << 16));
    lv.x = pack_bf2(p0 - __bfloat162float(h0), p1 - __bfloat162float(h1));
    lv.y = pack_bf2(p2 - __bfloat162float(h2), p3 - __bfloat162float(h3));
    *(uint2*)&g_p_hi[(size_t)b * NV * NV + base] = hv;
    *(uint2*)&g_p_lo[(size_t)b * NV * NV + base] = lv;
}

// ============================================================================
// Kernel 5: mask conv + bias + residual (fp32 SIMT, reads g_o).
// ============================================================================
__global__ __launch_bounds__(256) void mask_kernel(
    const float* __restrict__ wm, const float* __restrict__ bm,
    const float* __restrict__ x, float* __restrict__ outp)
{
    const int b = blockIdx.z;
    const float* Bmat = g_o + (size_t)b * ICH * HW;
    const float* xr   = x   + (size_t)b * CCH * HW;
    float* O          = outp + (size_t)b * CCH * HW;

    const int K = ICH, N = HW;
    const int m0 = blockIdx.y * BM;
    const int n0 = blockIdx.x * BN;

    __shared__ __align__(16) float As[BK][BM + 4];
    __shared__ __align__(16) float Bs[BK][BN];

    const int tid = threadIdx.x;
    const int tx = tid & 15, ty = tid >> 4;

    float acc[8][8];
#pragma unroll
    for (int i = 0; i < 8; i++)
#pragma unroll
        for (int j = 0; j < 8; j++) acc[i][j] = 0.f;

    for (int k0 = 0; k0 < K; k0 += BK) {
#pragma unroll
        for (int u = 0; u < 2; u++) {
            int idx = tid + u * 256;
            int rr = idx >> 2, cq = idx & 3;
            float4 v = *(const float4*)&wm[(size_t)(m0+rr)*K + k0 + cq*4];
            As[cq*4+0][rr] = v.x; As[cq*4+1][rr] = v.y;
            As[cq*4+2][rr] = v.z; As[cq*4+3][rr] = v.w;
        }
#pragma unroll
        for (int u = 0; u < 2; u++) {
            int idx = tid + u * 256;
            int kk = idx >> 5, nq = idx & 31;
            *(float4*)&Bs[kk][nq*4] =
                *(const float4*)&Bmat[(size_t)(k0+kk)*N + n0 + nq*4];
        }
        __syncthreads();
#pragma unroll
        for (int kk = 0; kk < BK; kk++) {
            float a[8], bb[8];
            *(float4*)&a[0]  = *(const float4*)&As[kk][ty*4];
            *(float4*)&a[4]  = *(const float4*)&As[kk][64 + ty*4];
            *(float4*)&bb[0] = *(const float4*)&Bs[kk][tx*4];
            *(float4*)&bb[4] = *(const float4*)&Bs[kk][64 + tx*4];
#pragma unroll
            for (int i = 0; i < 8; i++)
#pragma unroll
                for (int j = 0; j < 8; j++) acc[i][j] += a[i] * bb[j];
        }
        __syncthreads();
    }
#pragma unroll
    for (int i = 0; i < 8; i++) {
        int m = m0 + ((i < 4) ? (ty*4 + i) : (64 + ty*4 + i - 4));
        float bv = bm[m];
        float4 x0 = *(const float4*)&xr[(size_t)m*N + n0 + tx*4];
        float4 x1 = *(const float4*)&xr[(size_t)m*N + n0 + 64 + tx*4];
        float4 v0 = make_float4(acc[i][0]+bv+x0.x, acc[i][1]+bv+x0.y,
                                acc[i][2]+bv+x0.z, acc[i][3]+bv+x0.w);
        float4 v1 = make_float4(acc[i][4]+bv+x1.x, acc[i][5]+bv+x1.y,
                                acc[i][6]+bv+x1.z, acc[i][7]+bv+x1.w);
        *(float4*)&O[(size_t)m*N + n0 + tx*4]      = v0;
        *(float4*)&O[(size_t)m*N + n0 + 64 + tx*4] = v1;
    }
}

// ============================================================================
extern "C" void kernel_launch(void* const* d_in, const int* in_sizes, int n_in,
                              void* d_out, int out_size)
{
    const float* x       = (const float*)d_in[0];
    const float* w_phi   = (const float*)d_in[1];
    const float* b_phi   = (const float*)d_in[2];
    const float* w_theta = (const float*)d_in[3];
    const float* b_theta = (const float*)d_in[4];
    const float* w_g     = (const float*)d_in[5];
    const float* b_g     = (const float*)d_in[6];
    const float* w_mask  = (const float*)d_in[7];
    const float* b_mask  = (const float*)d_in[8];
    float* out = (float*)d_out;

    __nv_bfloat16 *thT_hi, *thT_lo, *phT_hi, *phT_lo, *ghi, *glo, *phi_p, *plo_p;
    float *sptr, *optr;
    cudaGetSymbolAddress((void**)&thT_hi, g_thT_hi);
    cudaGetSymbolAddress((void**)&thT_lo, g_thT_lo);
    cudaGetSymbolAddress((void**)&phT_hi, g_phT_hi);
    cudaGetSymbolAddress((void**)&phT_lo, g_phT_lo);
    cudaGetSymbolAddress((void**)&ghi,    g_g_hi);
    cudaGetSymbolAddress((void**)&glo,    g_g_lo);
    cudaGetSymbolAddress((void**)&phi_p,  g_p_hi);
    cudaGetSymbolAddress((void**)&plo_p,  g_p_lo);
    cudaGetSymbolAddress((void**)&sptr,   g_s);
    cudaGetSymbolAddress((void**)&optr,   g_o);

    cudaFuncSetAttribute(mma_gemm_kernel,
                         cudaFuncAttributeMaxDynamicSharedMemorySize,
                         TCG_SMEM_BYTES);

    // 1) projections -> split-bf16 operands
    proj_kernel<<<dim3(HW/BN, 1, BATCH*3), 256>>>(x, w_phi, b_phi,
                                                   w_theta, b_theta, w_g, b_g);
    // 2) scores: S[n][m] = theta^T . phi   (M=N=2048, K=256)
    mma_gemm_kernel<<<dim3(16, 16, BATCH), 256, TCG_SMEM_BYTES>>>(
        thT_hi, thT_lo, phT_hi, phT_lo, sptr, CCH,
        (size_t)NV*CCH, (size_t)NV*CCH, (size_t)NV*NV);
    // 3) column softmax stats
    reduce_kernel<<<dim3(NV/256, BATCH), 256>>>();
    // 4) P = exp(S - cmax)*cinv, split bf16
    ppass_kernel<<<dim3((NV*NV)/(256*4), BATCH), 256>>>();
    // 5) out: O[c][n] = g . P^T   (M=256, N=2048, K=2048)
    mma_gemm_kernel<<<dim3(16, 2, BATCH), 256, TCG_SMEM_BYTES>>>(
        ghi, glo, phi_p, plo_p, optr, NV,
        (size_t)CCH*NV, (size_t)NV*NV, (size_t)ICH*HW);
    // 6) mask conv + residual
    mask_kernel<<<dim3(HW/BN, CCH/BM, BATCH), 256>>>(w_mask, b_mask, x, out);
}

// round 8
// speedup vs baseline: 1.6267x; 1.2647x over previous
#include <cuda_runtime.h>
#include <cuda_fp16.h>
#include <math.h>
#include <stdint.h>

#define BATCH 16
#define CCH   256
#define ICH   128
#define HW    4096
#define NV    2048

#define BM 128
#define BN 128
#define BK 16

// ---------------- scratch (device globals; no allocation allowed) ----------
__device__ __align__(16) __half g_thT_hi[(size_t)BATCH * NV * CCH];
__device__ __align__(16) __half g_thT_lo[(size_t)BATCH * NV * CCH];
__device__ __align__(16) __half g_phT_hi[(size_t)BATCH * NV * CCH];
__device__ __align__(16) __half g_phT_lo[(size_t)BATCH * NV * CCH];
__device__ __align__(16) __half g_g_hi [(size_t)BATCH * CCH * NV];
__device__ __align__(16) __half g_g_lo [(size_t)BATCH * CCH * NV];
__device__ float g_s    [(size_t)BATCH * NV * NV];
__device__ float g_o    [(size_t)BATCH * ICH * HW];
__device__ float g_cmax [BATCH * NV];
__device__ float g_cinv [BATCH * NV];

// ---------------- helpers ---------------------------------------------------
#define SWZ(x) ((x) ^ (((x) >> 3) & 0x70))   // 128B-row swizzle

__device__ __forceinline__ uint32_t smem_to_u32(const void* p) {
    uint32_t a;
    asm("{ .reg .u64 t; cvta.to.shared.u64 t, %1; cvt.u32.u64 %0, t; }"
        : "=r"(a) : "l"(p));
    return a;
}
__device__ __forceinline__ void mma_f16(float* d, const uint32_t* a, const uint32_t* b) {
    asm volatile(
        "mma.sync.aligned.m16n8k16.row.col.f32.f16.f16.f32 "
        "{%0,%1,%2,%3}, {%4,%5,%6,%7}, {%8,%9}, {%0,%1,%2,%3};"
        : "+f"(d[0]), "+f"(d[1]), "+f"(d[2]), "+f"(d[3])
        : "r"(a[0]), "r"(a[1]), "r"(a[2]), "r"(a[3]), "r"(b[0]), "r"(b[1]));
}
__device__ __forceinline__ void ldm_x4(uint32_t* r, uint32_t addr) {
    asm volatile("ldmatrix.sync.aligned.m8n8.x4.shared.b16 {%0,%1,%2,%3}, [%4];"
                 : "=r"(r[0]), "=r"(r[1]), "=r"(r[2]), "=r"(r[3]) : "r"(addr));
}
__device__ __forceinline__ void cp_async16(uint32_t saddr, const void* gptr) {
    asm volatile("cp.async.cg.shared.global [%0], [%1], 16;\n" :: "r"(saddr), "l"(gptr));
}
__device__ __forceinline__ uint32_t pack_h2(float a, float b) {
    __half2 h = __floats2half2_rn(a, b);
    return *(uint32_t*)&h;
}
__device__ __forceinline__ void split2(float v0, float v1, uint32_t& hv, uint32_t& lv) {
    __half h0 = __float2half_rn(v0), h1 = __float2half_rn(v1);
    hv = (uint32_t)__half_as_ushort(h0) | ((uint32_t)__half_as_ushort(h1) << 16);
    lv = pack_h2(v0 - __half2float(h0), v1 - __half2float(h1));
}

// ============================================================================
// Scores GEMM (split-fp16 3-term):  S[n][m] = sum_k theta[n][k]*phi[m][k].
// Block 128x128, warp 64x32, 3-stage cp.async pipeline, K-stage 32.
// ============================================================================
#define SC_SMEM_BYTES (3 * 32768)

__global__ __launch_bounds__(256, 2) void mma_gemm_kernel(
    const __half* __restrict__ Ahi, const __half* __restrict__ Alo,
    const __half* __restrict__ Bhi, const __half* __restrict__ Blo,
    float* __restrict__ C, int K,
    size_t strideA, size_t strideB, size_t strideC)
{
    extern __shared__ __align__(128) uint8_t smem[];
    const uint32_t s0 = smem_to_u32(smem);

    const int b  = blockIdx.z;
    const int m0 = blockIdx.y * 128;
    const int n0 = blockIdx.x * 128;
    const int tid  = threadIdx.x;
    const int lane = tid & 31;
    const int w    = tid >> 5;
    const int m_base = (w & 1) * 64;
    const int n_base = (w >> 1) * 32;
    const int r  = lane >> 2;
    const int c2 = (lane & 3) * 2;

    const __half* Ah = Ahi + (size_t)b * strideA;
    const __half* Al = Alo + (size_t)b * strideA;
    const __half* Bh = Bhi + (size_t)b * strideB;
    const __half* Bl = Blo + (size_t)b * strideB;
    float* Cb = C + (size_t)b * strideC;

    const int S = K / 32;
    const int lrow = tid >> 1;
    const int lquad = tid & 1;

    float acc[4][4][4];
#pragma unroll
    for (int i = 0; i < 4; i++)
#pragma unroll
        for (int j = 0; j < 4; j++)
#pragma unroll
            for (int q = 0; q < 4; q++) acc[i][j][q] = 0.f;

    auto load_stage = [&](int s) {
        const uint32_t sb = s0 + (s % 3) * 32768;
        const int k0 = s * 32;
#pragma unroll
        for (int u4 = 0; u4 < 4; u4++) {
            int u = lquad * 4 + u4;
            uint32_t dsw = SWZ((uint32_t)(lrow * 128 + u * 16));
            const __half* srcA = (u < 4) ? Ah : Al;
            const __half* srcB = (u < 4) ? Bh : Bl;
            int ke = k0 + (u & 3) * 8;
            cp_async16(sb + dsw,         srcA + (size_t)(m0 + lrow) * K + ke);
            cp_async16(sb + 16384 + dsw, srcB + (size_t)(n0 + lrow) * K + ke);
        }
        asm volatile("cp.async.commit_group;\n");
    };

    load_stage(0);
    load_stage(1);

    const int jj   = lane >> 4;
    const int sub  = (lane >> 3) & 1;
    const int l7   = lane & 7;
    const int l15  = lane & 15;

    for (int s = 0; s < S; s++) {
        if (s + 1 < S) asm volatile("cp.async.wait_group 1;\n");
        else           asm volatile("cp.async.wait_group 0;\n");
        __syncthreads();

        const uint32_t SAb = s0 + (s % 3) * 32768;
        const uint32_t SBb = SAb + 16384;

#pragma unroll
        for (int kk16 = 0; kk16 < 32; kk16 += 16) {
            uint32_t bh[4][2], bl[4][2];
#pragma unroll
            for (int jp = 0; jp < 2; jp++) {
                int row = n_base + (jp * 2 + jj) * 8 + l7;
                uint32_t off = (uint32_t)(row * 128 + (kk16 + sub * 8) * 2);
                uint32_t r4[4];
                ldm_x4(r4, SBb + SWZ(off));
                bh[jp*2][0] = r4[0]; bh[jp*2][1] = r4[1];
                bh[jp*2+1][0] = r4[2]; bh[jp*2+1][1] = r4[3];
                ldm_x4(r4, SBb + SWZ(off + 64));
                bl[jp*2][0] = r4[0]; bl[jp*2][1] = r4[1];
                bl[jp*2+1][0] = r4[2]; bl[jp*2+1][1] = r4[3];
            }
#pragma unroll
            for (int i = 0; i < 4; i++) {
                int row = m_base + i * 16 + l15;
                uint32_t off = (uint32_t)(row * 128 + (kk16 + jj * 8) * 2);
                uint32_t ah[4], al[4];
                ldm_x4(ah, SAb + SWZ(off));
                ldm_x4(al, SAb + SWZ(off + 64));
#pragma unroll
                for (int j = 0; j < 4; j++) {
                    mma_f16(acc[i][j], ah, bh[j]);
                    mma_f16(acc[i][j], ah, bl[j]);
                    mma_f16(acc[i][j], al, bh[j]);
                }
            }
        }
        __syncthreads();
        if (s + 2 < S) load_stage(s + 2);
    }

#pragma unroll
    for (int i = 0; i < 4; i++) {
        int row = m0 + m_base + i * 16 + r;
#pragma unroll
        for (int j = 0; j < 4; j++) {
            int col = n0 + n_base + j * 8 + c2;
            *(float2*)&Cb[(size_t)row * NV + col] =
                make_float2(acc[i][j][0], acc[i][j][1]);
            *(float2*)&Cb[(size_t)(row + 8) * NV + col] =
                make_float2(acc[i][j][2], acc[i][j][3]);
        }
    }
}

// ============================================================================
// Fused outgemm:  O[c][n] = sum_m (gh+gl)[c][m] * fp16(exp(S[n][m]-cmax[m])*cinv[m])
// A = g (fp16 2-term, cp.async 3-stage).  B = p computed in-loader from fp32 S
// (LDG -> exp -> fp16 -> STS, 2-stage).  2 MMAs per k16 per (i,j).
// smem: A 3x16KB | B 2x16KB | cmax 8KB | cinv 8KB = 96KB.
// ============================================================================
#define OG_SMEM_BYTES (49152 + 32768 + 16384)

__global__ __launch_bounds__(256, 2) void outgemm_fused_kernel()
{
    extern __shared__ __align__(128) uint8_t smem[];
    const uint32_t s0 = smem_to_u32(smem);
    const uint32_t SA0 = s0;
    const uint32_t SB0 = s0 + 49152;
    const uint32_t SST = s0 + 81920;
    const float* cm_s = (const float*)(smem + 81920);
    const float* ci_s = (const float*)(smem + 81920 + 8192);

    const int b  = blockIdx.z;
    const int n0 = blockIdx.x * 128;
    const int c0 = blockIdx.y * 128;
    const int tid  = threadIdx.x;
    const int lane = tid & 31;
    const int w    = tid >> 5;
    const int m_base = (w & 1) * 64;
    const int n_base = (w >> 1) * 32;
    const int r  = lane >> 2;
    const int c2 = (lane & 3) * 2;

    const __half* Gh = g_g_hi + (size_t)b * CCH * NV;
    const __half* Gl = g_g_lo + (size_t)b * CCH * NV;
    const float*  Sm = g_s    + (size_t)b * NV * NV;
    float* O = g_o + (size_t)b * ICH * HW;

    const int S = NV / 32;   // 64 stages

    float acc[4][4][4];
#pragma unroll
    for (int i = 0; i < 4; i++)
#pragma unroll
        for (int j = 0; j < 4; j++)
#pragma unroll
            for (int q = 0; q < 4; q++) acc[i][j][q] = 0.f;

    auto load_stage = [&](int s) {
        const uint32_t sb = SA0 + (s % 3) * 16384;
        const int k0 = s * 32;
#pragma unroll
        for (int i = 0; i < 4; i++) {
            int id = tid + i * 256;
            int row = id >> 3, u = id & 7;
            uint32_t dsw = SWZ((uint32_t)(row * 128 + u * 16));
            const __half* src = (u < 4) ? Gh : Gl;
            cp_async16(sb + dsw, src + (size_t)(c0 + row) * NV + k0 + (u & 3) * 8);
        }
        asm volatile("cp.async.commit_group;\n");
    };

    // prologue: stats (cmax|cinv contiguous 16KB) + A0 in group 0, A1 in group 1
#pragma unroll
    for (int i = 0; i < 4; i++) {
        int id = tid + i * 256;   // 1024 16B chunks
        const float* src = (id < 512) ? (g_cmax + b * NV + id * 4)
                                      : (g_cinv + b * NV + (id - 512) * 4);
        cp_async16(SST + id * 16, src);
    }
    load_stage(0);
    load_stage(1);

    const int brow  = tid >> 1;       // B loader: row n, half (tid&1)
    const int bhalf = tid & 1;
    float4 breg[4];
    {
        const float* Srow = Sm + (size_t)(n0 + brow) * NV + bhalf * 16;
#pragma unroll
        for (int q = 0; q < 4; q++) breg[q] = *(const float4*)(Srow + q * 4);
    }

    const int jj   = lane >> 4;
    const int sub  = (lane >> 3) & 1;
    const int l7   = lane & 7;
    const int l15  = lane & 15;

    for (int s = 0; s < S; s++) {
        if (s + 1 < S) asm volatile("cp.async.wait_group 1;\n");
        else           asm volatile("cp.async.wait_group 0;\n");
        __syncthreads();      // A(s)+stats visible; prior B reads complete

        {   // transform stage s and store p fp16 to B buffer s&1
            const int kb = s * 32 + bhalf * 16;
            uint32_t p16[8];
#pragma unroll
            for (int q = 0; q < 4; q++) {
                int k = kb + q * 4;
                float e0 = expf(breg[q].x - cm_s[k+0]) * ci_s[k+0];
                float e1 = expf(breg[q].y - cm_s[k+1]) * ci_s[k+1];
                float e2 = expf(breg[q].z - cm_s[k+2]) * ci_s[k+2];
                float e3 = expf(breg[q].w - cm_s[k+3]) * ci_s[k+3];
                p16[q*2+0] = pack_h2(e0, e1);
                p16[q*2+1] = pack_h2(e2, e3);
            }
            uint32_t base = SB0 + (s & 1) * 16384;
            uint32_t a0 = base + SWZ((uint32_t)(brow * 128 + bhalf * 32));
            uint32_t a1 = base + SWZ((uint32_t)(brow * 128 + bhalf * 32 + 16));
            *(uint4*)(smem + (a0 - s0)) = make_uint4(p16[0], p16[1], p16[2], p16[3]);
            *(uint4*)(smem + (a1 - s0)) = make_uint4(p16[4], p16[5], p16[6], p16[7]);
        }
        if (s + 1 < S) {   // prefetch next B stage (fp32), latency hidden by compute
            const float* Srow = Sm + (size_t)(n0 + brow) * NV + (s + 1) * 32 + bhalf * 16;
#pragma unroll
            for (int q = 0; q < 4; q++) breg[q] = *(const float4*)(Srow + q * 4);
        }
        __syncthreads();      // p tile visible

        const uint32_t SAb = SA0 + (s % 3) * 16384;
        const uint32_t SBb = SB0 + (s & 1) * 16384;
#pragma unroll
        for (int kk16 = 0; kk16 < 32; kk16 += 16) {
            uint32_t bp[4][2];
#pragma unroll
            for (int jp = 0; jp < 2; jp++) {
                int row = n_base + (jp * 2 + jj) * 8 + l7;
                uint32_t off = (uint32_t)(row * 128 + (kk16 + sub * 8) * 2);
                uint32_t r4[4];
                ldm_x4(r4, SBb + SWZ(off));
                bp[jp*2][0] = r4[0]; bp[jp*2][1] = r4[1];
                bp[jp*2+1][0] = r4[2]; bp[jp*2+1][1] = r4[3];
            }
#pragma unroll
            for (int i = 0; i < 4; i++) {
                int row = m_base + i * 16 + l15;
                uint32_t off = (uint32_t)(row * 128 + (kk16 + jj * 8) * 2);
                uint32_t ah[4], al[4];
                ldm_x4(ah, SAb + SWZ(off));
                ldm_x4(al, SAb + SWZ(off + 64));
#pragma unroll
                for (int j = 0; j < 4; j++) {
                    mma_f16(acc[i][j], ah, bp[j]);
                    mma_f16(acc[i][j], al, bp[j]);
                }
            }
        }
        if (s + 2 < S) load_stage(s + 2);
    }

#pragma unroll
    for (int i = 0; i < 4; i++) {
        int row = c0 + m_base + i * 16 + r;
#pragma unroll
        for (int j = 0; j < 4; j++) {
            int col = n0 + n_base + j * 8 + c2;
            *(float2*)&O[(size_t)row * NV + col] =
                make_float2(acc[i][j][0], acc[i][j][1]);
            *(float2*)&O[(size_t)(row + 8) * NV + col] =
                make_float2(acc[i][j][2], acc[i][j][3]);
        }
    }
}

// ============================================================================
// Kernel 1: projections (fp32 FFMA GEMM) + split-fp16 epilogues.
// ============================================================================
union ProjSmem {
    struct { float As[BK][BM + 4]; float Bs[BK][BN]; } g;
    __half t[128][136];
};

__global__ __launch_bounds__(256) void proj_kernel(
    const float* __restrict__ x,
    const float* __restrict__ w0, const float* __restrict__ b0,
    const float* __restrict__ w1, const float* __restrict__ b1,
    const float* __restrict__ w2, const float* __restrict__ b2)
{
    const int z = blockIdx.z;
    const int batch = z / 3;
    const int pj = z - batch * 3;
    const float* W    = (pj == 0) ? w0 : (pj == 1) ? w1 : w2;
    const float* bias = (pj == 0) ? b0 : (pj == 1) ? b1 : b2;
    const float* Bmat = x + (size_t)batch * CCH * HW;

    const int K = CCH, N = HW;
    const int n0 = blockIdx.x * BN;

    __shared__ ProjSmem sm;

    const int tid = threadIdx.x;
    const int tx = tid & 15, ty = tid >> 4;

    float acc[8][8];
#pragma unroll
    for (int i = 0; i < 8; i++)
#pragma unroll
        for (int j = 0; j < 8; j++) acc[i][j] = 0.f;

    for (int k0 = 0; k0 < K; k0 += BK) {
#pragma unroll
        for (int u = 0; u < 2; u++) {
            int idx = tid + u * 256;
            int rr = idx >> 2, cq = idx & 3;
            float4 v = *(const float4*)&W[rr * K + k0 + cq * 4];
            sm.g.As[cq*4+0][rr] = v.x; sm.g.As[cq*4+1][rr] = v.y;
            sm.g.As[cq*4+2][rr] = v.z; sm.g.As[cq*4+3][rr] = v.w;
        }
#pragma unroll
        for (int u = 0; u < 2; u++) {
            int idx = tid + u * 256;
            int kk = idx >> 5, nq = idx & 31;
            *(float4*)&sm.g.Bs[kk][nq*4] =
                *(const float4*)&Bmat[(size_t)(k0+kk)*N + n0 + nq*4];
        }
        __syncthreads();
#pragma unroll
        for (int kk = 0; kk < BK; kk++) {
            float a[8], bb[8];
            *(float4*)&a[0] = *(const float4*)&sm.g.As[kk][ty*4];
            *(float4*)&a[4] = *(const float4*)&sm.g.As[kk][64 + ty*4];
            *(float4*)&bb[0] = *(const float4*)&sm.g.Bs[kk][tx*4];
            *(float4*)&bb[4] = *(const float4*)&sm.g.Bs[kk][64 + tx*4];
#pragma unroll
            for (int i = 0; i < 8; i++)
#pragma unroll
                for (int j = 0; j < 8; j++) acc[i][j] += a[i] * bb[j];
        }
        __syncthreads();
    }

#pragma unroll
    for (int i = 0; i < 8; i++) {
        int m = (i < 4) ? (ty*4 + i) : (64 + ty*4 + i - 4);
        float bv = bias[m];
#pragma unroll
        for (int j = 0; j < 8; j++) acc[i][j] += bv;
    }

    const int half = n0 / 2048;
    const int nr0  = n0 - half * 2048;

    if (pj == 2) {
        __half* gh = g_g_hi + (size_t)batch * CCH * NV;
        __half* gl = g_g_lo + (size_t)batch * CCH * NV;
#pragma unroll
        for (int i = 0; i < 8; i++) {
            int ic = (i < 4) ? (ty*4 + i) : (64 + ty*4 + i - 4);
            int c = 2*ic + half;
#pragma unroll
            for (int jg = 0; jg < 2; jg++) {
                int colb = nr0 + jg*64 + tx*4;
                uint2 hv, lv;
                split2(acc[i][jg*4+0], acc[i][jg*4+1], hv.x, lv.x);
                split2(acc[i][jg*4+2], acc[i][jg*4+3], hv.y, lv.y);
                *(uint2*)&gh[(size_t)c*NV + colb] = hv;
                *(uint2*)&gl[(size_t)c*NV + colb] = lv;
            }
        }
    } else {
        __half* Thi = ((pj == 0) ? g_phT_hi : g_thT_hi) + (size_t)batch * NV * CCH;
        __half* Tlo = ((pj == 0) ? g_phT_lo : g_thT_lo) + (size_t)batch * NV * CCH;

        for (int pass = 0; pass < 2; pass++) {
#pragma unroll
            for (int i = 0; i < 8; i++) {
                int m = (i < 4) ? (ty*4 + i) : (64 + ty*4 + i - 4);
#pragma unroll
                for (int j = 0; j < 8; j++) {
                    int col = (j < 4) ? (tx*4 + j) : (64 + tx*4 + j - 4);
                    float v = acc[i][j];
                    __half h = __float2half_rn(v);
                    sm.t[col][m] = (pass == 0) ? h
                                 : __float2half_rn(v - __half2float(h));
                }
            }
            __syncthreads();
            {
                int row = tid >> 1, seg = tid & 1;
                __half* dstb = (pass == 0 ? Thi : Tlo)
                    + (size_t)(nr0 + row) * CCH + half*128 + seg*64;
                const uint4* src = (const uint4*)&sm.t[row][seg*64];
                uint4* dst = (uint4*)dstb;
#pragma unroll
                for (int q = 0; q < 8; q++) dst[q] = src[q];
            }
            __syncthreads();
        }
    }
}

// ============================================================================
// Kernel 3: per-column (m) online softmax stats over rows n.
// ============================================================================
__global__ __launch_bounds__(256) void reduce_kernel()
{
    const int b = blockIdx.y;
    const int m = blockIdx.x * 256 + threadIdx.x;
    const float* S = g_s + (size_t)b * NV * NV;

    float mx = __int_as_float(0xff800000);
    float sm = 0.f;
    for (int n = 0; n < NV; n += 8) {
        float v[8];
#pragma unroll
        for (int q = 0; q < 8; q++) v[q] = S[(size_t)(n+q)*NV + m];
#pragma unroll
        for (int q = 0; q < 8; q++) {
            float nm = fmaxf(mx, v[q]);
            sm = sm * expf(mx - nm) + expf(v[q] - nm);
            mx = nm;
        }
    }
    g_cmax[b*NV + m] = mx;
    g_cinv[b*NV + m] = 1.0f / sm;
}

// ============================================================================
// Kernel 5: mask conv + bias + residual (fp32 SIMT, reads g_o).
// ============================================================================
__global__ __launch_bounds__(256) void mask_kernel(
    const float* __restrict__ wm, const float* __restrict__ bm,
    const float* __restrict__ x, float* __restrict__ outp)
{
    const int b = blockIdx.z;
    const float* Bmat = g_o + (size_t)b * ICH * HW;
    const float* xr   = x   + (size_t)b * CCH * HW;
    float* O          = outp + (size_t)b * CCH * HW;

    const int K = ICH, N = HW;
    const int m0 = blockIdx.y * BM;
    const int n0 = blockIdx.x * BN;

    __shared__ __align__(16) float As[BK][BM + 4];
    __shared__ __align__(16) float Bs[BK][BN];

    const int tid = threadIdx.x;
    const int tx = tid & 15, ty = tid >> 4;

    float acc[8][8];
#pragma unroll
    for (int i = 0; i < 8; i++)
#pragma unroll
        for (int j = 0; j < 8; j++) acc[i][j] = 0.f;

    for (int k0 = 0; k0 < K; k0 += BK) {
#pragma unroll
        for (int u = 0; u < 2; u++) {
            int idx = tid + u * 256;
            int rr = idx >> 2, cq = idx & 3;
            float4 v = *(const float4*)&wm[(size_t)(m0+rr)*K + k0 + cq*4];
            As[cq*4+0][rr] = v.x; As[cq*4+1][rr] = v.y;
            As[cq*4+2][rr] = v.z; As[cq*4+3][rr] = v.w;
        }
#pragma unroll
        for (int u = 0; u < 2; u++) {
            int idx = tid + u * 256;
            int kk = idx >> 5, nq = idx & 31;
            *(float4*)&Bs[kk][nq*4] =
                *(const float4*)&Bmat[(size_t)(k0+kk)*N + n0 + nq*4];
        }
        __syncthreads();
#pragma unroll
        for (int kk = 0; kk < BK; kk++) {
            float a[8], bb[8];
            *(float4*)&a[0]  = *(const float4*)&As[kk][ty*4];
            *(float4*)&a[4]  = *(const float4*)&As[kk][64 + ty*4];
            *(float4*)&bb[0] = *(const float4*)&Bs[kk][tx*4];
            *(float4*)&bb[4] = *(const float4*)&Bs[kk][64 + tx*4];
#pragma unroll
            for (int i = 0; i < 8; i++)
#pragma unroll
                for (int j = 0; j < 8; j++) acc[i][j] += a[i] * bb[j];
        }
        __syncthreads();
    }
#pragma unroll
    for (int i = 0; i < 8; i++) {
        int m = m0 + ((i < 4) ? (ty*4 + i) : (64 + ty*4 + i - 4));
        float bv = bm[m];
        float4 x0 = *(const float4*)&xr[(size_t)m*N + n0 + tx*4];
        float4 x1 = *(const float4*)&xr[(size_t)m*N + n0 + 64 + tx*4];
        float4 v0 = make_float4(acc[i][0]+bv+x0.x, acc[i][1]+bv+x0.y,
                                acc[i][2]+bv+x0.z, acc[i][3]+bv+x0.w);
        float4 v1 = make_float4(acc[i][4]+bv+x1.x, acc[i][5]+bv+x1.y,
                                acc[i][6]+bv+x1.z, acc[i][7]+bv+x1.w);
        *(float4*)&O[(size_t)m*N + n0 + tx*4]      = v0;
        *(float4*)&O[(size_t)m*N + n0 + 64 + tx*4] = v1;
    }
}

// ============================================================================
extern "C" void kernel_launch(void* const* d_in, const int* in_sizes, int n_in,
                              void* d_out, int out_size)
{
    const float* x       = (const float*)d_in[0];
    const float* w_phi   = (const float*)d_in[1];
    const float* b_phi   = (const float*)d_in[2];
    const float* w_theta = (const float*)d_in[3];
    const float* b_theta = (const float*)d_in[4];
    const float* w_g     = (const float*)d_in[5];
    const float* b_g     = (const float*)d_in[6];
    const float* w_mask  = (const float*)d_in[7];
    const float* b_mask  = (const float*)d_in[8];
    float* out = (float*)d_out;

    __half *thT_hi, *thT_lo, *phT_hi, *phT_lo;
    float *sptr;
    cudaGetSymbolAddress((void**)&thT_hi, g_thT_hi);
    cudaGetSymbolAddress((void**)&thT_lo, g_thT_lo);
    cudaGetSymbolAddress((void**)&phT_hi, g_phT_hi);
    cudaGetSymbolAddress((void**)&phT_lo, g_phT_lo);
    cudaGetSymbolAddress((void**)&sptr,   g_s);

    cudaFuncSetAttribute(mma_gemm_kernel,
                         cudaFuncAttributeMaxDynamicSharedMemorySize,
                         SC_SMEM_BYTES);
    cudaFuncSetAttribute(outgemm_fused_kernel,
                         cudaFuncAttributeMaxDynamicSharedMemorySize,
                         OG_SMEM_BYTES);

    // 1) projections -> split-fp16 operands
    proj_kernel<<<dim3(HW/BN, 1, BATCH*3), 256>>>(x, w_phi, b_phi,
                                                   w_theta, b_theta, w_g, b_g);
    // 2) scores: S[n][m] = theta^T . phi   (M=N=2048, K=256), fp32 out
    mma_gemm_kernel<<<dim3(16, 16, BATCH), 256, SC_SMEM_BYTES>>>(
        thT_hi, thT_lo, phT_hi, phT_lo, sptr, CCH,
        (size_t)NV*CCH, (size_t)NV*CCH, (size_t)NV*NV);
    // 3) column softmax stats
    reduce_kernel<<<dim3(NV/256, BATCH), 256>>>();
    // 4) fused outgemm: exp + scale + GEMM (M=256, N=2048, K=2048)
    outgemm_fused_kernel<<<dim3(16, 2, BATCH), 256, OG_SMEM_BYTES>>>();
    // 5) mask conv + residual
    mask_kernel<<<dim3(HW/BN, CCH/BM, BATCH), 256>>>(w_mask, b_mask, x, out);
}

// round 11
// speedup vs baseline: 1.7105x; 1.0515x over previous
#include <cuda_runtime.h>
#include <cuda_fp16.h>
#include <math.h>
#include <stdint.h>

#define BATCH 16
#define CCH   256
#define ICH   128
#define HW    4096
#define NV    2048

#define BM 128
#define BN 128
#define BK 16

// ---------------- scratch (device globals; no allocation allowed) ----------
__device__ __align__(16) __half g_thT_hi[(size_t)BATCH * NV * CCH];
__device__ __align__(16) __half g_thT_lo[(size_t)BATCH * NV * CCH];
__device__ __align__(16) __half g_phT_hi[(size_t)BATCH * NV * CCH];
__device__ __align__(16) __half g_phT_lo[(size_t)BATCH * NV * CCH];
__device__ __align__(16) __half g_g_hi [(size_t)BATCH * CCH * NV];
__device__ __align__(16) __half g_g_lo [(size_t)BATCH * CCH * NV];
__device__ __align__(16) __half g_oT_hi[(size_t)BATCH * HW * ICH];   // o^T[hw][ic]
__device__ __align__(16) __half g_oT_lo[(size_t)BATCH * HW * ICH];
__device__ float g_s    [(size_t)BATCH * NV * NV];
__device__ float g_cmax [BATCH * NV];
__device__ float g_cinv [BATCH * NV];

// ---------------- helpers ---------------------------------------------------
#define SWZ(x) ((x) ^ (((x) >> 3) & 0x70))   // 128B-row swizzle

__device__ __forceinline__ uint32_t smem_to_u32(const void* p) {
    uint32_t a;
    asm("{ .reg .u64 t; cvta.to.shared.u64 t, %1; cvt.u32.u64 %0, t; }"
        : "=r"(a) : "l"(p));
    return a;
}
__device__ __forceinline__ void mma_f16(float* d, const uint32_t* a, const uint32_t* b) {
    asm volatile(
        "mma.sync.aligned.m16n8k16.row.col.f32.f16.f16.f32 "
        "{%0,%1,%2,%3}, {%4,%5,%6,%7}, {%8,%9}, {%0,%1,%2,%3};"
        : "+f"(d[0]), "+f"(d[1]), "+f"(d[2]), "+f"(d[3])
        : "r"(a[0]), "r"(a[1]), "r"(a[2]), "r"(a[3]), "r"(b[0]), "r"(b[1]));
}
__device__ __forceinline__ void ldm_x4(uint32_t* r, uint32_t addr) {
    asm volatile("ldmatrix.sync.aligned.m8n8.x4.shared.b16 {%0,%1,%2,%3}, [%4];"
                 : "=r"(r[0]), "=r"(r[1]), "=r"(r[2]), "=r"(r[3]) : "r"(addr));
}
__device__ __forceinline__ void cp_async16(uint32_t saddr, const void* gptr) {
    asm volatile("cp.async.cg.shared.global [%0], [%1], 16;\n" :: "r"(saddr), "l"(gptr));
}
__device__ __forceinline__ uint32_t pack_h2(float a, float b) {
    __half2 h = __floats2half2_rn(a, b);
    return *(uint32_t*)&h;
}
__device__ __forceinline__ void split2(float v0, float v1, uint32_t& hv, uint32_t& lv) {
    __half h0 = __float2half_rn(v0), h1 = __float2half_rn(v1);
    hv = (uint32_t)__half_as_ushort(h0) | ((uint32_t)__half_as_ushort(h1) << 16);
    lv = pack_h2(v0 - __half2float(h0), v1 - __half2float(h1));
}

// ============================================================================
// Scores GEMM (split-fp16 3-term):  S[n][m] = sum_k theta[n][k]*phi[m][k].
// Block 128x128, warp 64x32, 3-stage cp.async pipeline, K-stage 32.
// ONE __syncthreads per stage (bottom barrier proved redundant).
// ============================================================================
#define SC_SMEM_BYTES (3 * 32768)

__global__ __launch_bounds__(256, 2) void mma_gemm_kernel(
    const __half* __restrict__ Ahi, const __half* __restrict__ Alo,
    const __half* __restrict__ Bhi, const __half* __restrict__ Blo,
    float* __restrict__ C, int K,
    size_t strideA, size_t strideB, size_t strideC)
{
    extern __shared__ __align__(128) uint8_t smem[];
    const uint32_t s0 = smem_to_u32(smem);

    const int b  = blockIdx.z;
    const int m0 = blockIdx.y * 128;
    const int n0 = blockIdx.x * 128;
    const int tid  = threadIdx.x;
    const int lane = tid & 31;
    const int w    = tid >> 5;
    const int m_base = (w & 1) * 64;
    const int n_base = (w >> 1) * 32;
    const int r  = lane >> 2;
    const int c2 = (lane & 3) * 2;

    const __half* Ah = Ahi + (size_t)b * strideA;
    const __half* Al = Alo + (size_t)b * strideA;
    const __half* Bh = Bhi + (size_t)b * strideB;
    const __half* Bl = Blo + (size_t)b * strideB;
    float* Cb = C + (size_t)b * strideC;

    const int S = K / 32;
    const int lrow = tid >> 1;
    const int lquad = tid & 1;

    float acc[4][4][4];
#pragma unroll
    for (int i = 0; i < 4; i++)
#pragma unroll
        for (int j = 0; j < 4; j++)
#pragma unroll
            for (int q = 0; q < 4; q++) acc[i][j][q] = 0.f;

    auto load_stage = [&](int s) {
        const uint32_t sb = s0 + (s % 3) * 32768;
        const int k0 = s * 32;
#pragma unroll
        for (int u4 = 0; u4 < 4; u4++) {
            int u = lquad * 4 + u4;
            uint32_t dsw = SWZ((uint32_t)(lrow * 128 + u * 16));
            const __half* srcA = (u < 4) ? Ah : Al;
            const __half* srcB = (u < 4) ? Bh : Bl;
            int ke = k0 + (u & 3) * 8;
            cp_async16(sb + dsw,         srcA + (size_t)(m0 + lrow) * K + ke);
            cp_async16(sb + 16384 + dsw, srcB + (size_t)(n0 + lrow) * K + ke);
        }
        asm volatile("cp.async.commit_group;\n");
    };

    load_stage(0);
    load_stage(1);

    const int jj   = lane >> 4;
    const int sub  = (lane >> 3) & 1;
    const int l7   = lane & 7;
    const int l15  = lane & 15;

    for (int s = 0; s < S; s++) {
        if (s + 1 < S) asm volatile("cp.async.wait_group 1;\n");
        else           asm volatile("cp.async.wait_group 0;\n");
        __syncthreads();
        if (s + 2 < S) load_stage(s + 2);   // overwrites buf (s-1)%3: reads done pre-barrier

        const uint32_t SAb = s0 + (s % 3) * 32768;
        const uint32_t SBb = SAb + 16384;

#pragma unroll
        for (int kk16 = 0; kk16 < 32; kk16 += 16) {
            uint32_t bh[4][2], bl[4][2];
#pragma unroll
            for (int jp = 0; jp < 2; jp++) {
                int row = n_base + (jp * 2 + jj) * 8 + l7;
                uint32_t off = (uint32_t)(row * 128 + (kk16 + sub * 8) * 2);
                uint32_t r4[4];
                ldm_x4(r4, SBb + SWZ(off));
                bh[jp*2][0] = r4[0]; bh[jp*2][1] = r4[1];
                bh[jp*2+1][0] = r4[2]; bh[jp*2+1][1] = r4[3];
                ldm_x4(r4, SBb + SWZ(off + 64));
                bl[jp*2][0] = r4[0]; bl[jp*2][1] = r4[1];
                bl[jp*2+1][0] = r4[2]; bl[jp*2+1][1] = r4[3];
            }
#pragma unroll
            for (int i = 0; i < 4; i++) {
                int row = m_base + i * 16 + l15;
                uint32_t off = (uint32_t)(row * 128 + (kk16 + jj * 8) * 2);
                uint32_t ah[4], al[4];
                ldm_x4(ah, SAb + SWZ(off));
                ldm_x4(al, SAb + SWZ(off + 64));
#pragma unroll
                for (int j = 0; j < 4; j++) {
                    mma_f16(acc[i][j], ah, bh[j]);
                    mma_f16(acc[i][j], ah, bl[j]);
                    mma_f16(acc[i][j], al, bh[j]);
                }
            }
        }
    }

#pragma unroll
    for (int i = 0; i < 4; i++) {
        int row = m0 + m_base + i * 16 + r;
#pragma unroll
        for (int j = 0; j < 4; j++) {
            int col = n0 + n_base + j * 8 + c2;
            *(float2*)&Cb[(size_t)row * NV + col] =
                make_float2(acc[i][j][0], acc[i][j][1]);
            *(float2*)&Cb[(size_t)(row + 8) * NV + col] =
                make_float2(acc[i][j][2], acc[i][j][3]);
        }
    }
}

// ============================================================================
// Fused outgemm:  O[c][n] = sum_m (gh+gl)[c][m] * fp16(exp(S[n][m]-cmax[m])*cinv[m])
// ONE barrier per stage: transform for stage s+1 runs after MMAs of stage s.
// Epilogue: smem transpose -> split-fp16 o^T[hw][ic] for the mask MMA kernel.
// ============================================================================
#define OG_SMEM_BYTES (49152 + 32768 + 16384)

__global__ __launch_bounds__(256, 2) void outgemm_fused_kernel()
{
    extern __shared__ __align__(128) uint8_t smem[];
    const uint32_t s0 = smem_to_u32(smem);
    const uint32_t SA0 = s0;
    const uint32_t SB0 = s0 + 49152;
    const uint32_t SST = s0 + 81920;
    const float* cm_s = (const float*)(smem + 81920);
    const float* ci_s = (const float*)(smem + 81920 + 8192);

    const int b  = blockIdx.z;
    const int n0 = blockIdx.x * 128;
    const int c0 = blockIdx.y * 128;
    const int tid  = threadIdx.x;
    const int lane = tid & 31;
    const int w    = tid >> 5;
    const int m_base = (w & 1) * 64;
    const int n_base = (w >> 1) * 32;
    const int r  = lane >> 2;
    const int c2 = (lane & 3) * 2;

    const __half* Gh = g_g_hi + (size_t)b * CCH * NV;
    const __half* Gl = g_g_lo + (size_t)b * CCH * NV;
    const float*  Sm = g_s    + (size_t)b * NV * NV;

    const int S = NV / 32;   // 64 stages

    float acc[4][4][4];
#pragma unroll
    for (int i = 0; i < 4; i++)
#pragma unroll
        for (int j = 0; j < 4; j++)
#pragma unroll
            for (int q = 0; q < 4; q++) acc[i][j][q] = 0.f;

    auto load_stage = [&](int s) {
        const uint32_t sb = SA0 + (s % 3) * 16384;
        const int k0 = s * 32;
#pragma unroll
        for (int i = 0; i < 4; i++) {
            int id = tid + i * 256;
            int row = id >> 3, u = id & 7;
            uint32_t dsw = SWZ((uint32_t)(row * 128 + u * 16));
            const __half* src = (u < 4) ? Gh : Gl;
            cp_async16(sb + dsw, src + (size_t)(c0 + row) * NV + k0 + (u & 3) * 8);
        }
        asm volatile("cp.async.commit_group;\n");
    };

    const int brow  = tid >> 1;
    const int bhalf = tid & 1;

    auto prefetch_b = [&](int s, float4* br) {
        const float* Srow = Sm + (size_t)(n0 + brow) * NV + s * 32 + bhalf * 16;
#pragma unroll
        for (int q = 0; q < 4; q++) br[q] = *(const float4*)(Srow + q * 4);
    };
    auto transform = [&](int s, const float4* br) {
        const int kb = s * 32 + bhalf * 16;
        uint32_t p16[8];
#pragma unroll
        for (int q = 0; q < 4; q++) {
            int k = kb + q * 4;
            float e0 = expf(br[q].x - cm_s[k+0]) * ci_s[k+0];
            float e1 = expf(br[q].y - cm_s[k+1]) * ci_s[k+1];
            float e2 = expf(br[q].z - cm_s[k+2]) * ci_s[k+2];
            float e3 = expf(br[q].w - cm_s[k+3]) * ci_s[k+3];
            p16[q*2+0] = pack_h2(e0, e1);
            p16[q*2+1] = pack_h2(e2, e3);
        }
        uint32_t base = SB0 + (s & 1) * 16384;
        uint32_t a0 = base + SWZ((uint32_t)(brow * 128 + bhalf * 32));
        uint32_t a1 = base + SWZ((uint32_t)(brow * 128 + bhalf * 32 + 16));
        *(uint4*)(smem + (a0 - s0)) = make_uint4(p16[0], p16[1], p16[2], p16[3]);
        *(uint4*)(smem + (a1 - s0)) = make_uint4(p16[4], p16[5], p16[6], p16[7]);
    };

    // prologue: stats join cp.async group 0
#pragma unroll
    for (int i = 0; i < 4; i++) {
        int id = tid + i * 256;
        const float* src = (id < 512) ? (g_cmax + b * NV + id * 4)
                                      : (g_cinv + b * NV + (id - 512) * 4);
        cp_async16(SST + id * 16, src);
    }
    load_stage(0);
    load_stage(1);

    float4 breg[4];
    prefetch_b(0, breg);
    asm volatile("cp.async.wait_group 1;\n");   // group 0 (stats + A0) done
    __syncthreads();
    transform(0, breg);                          // -> B buf 0
    prefetch_b(1, breg);

    const int jj   = lane >> 4;
    const int sub  = (lane >> 3) & 1;
    const int l7   = lane & 7;
    const int l15  = lane & 15;

    for (int s = 0; s < S; s++) {
        if (s + 1 < S) asm volatile("cp.async.wait_group 1;\n");
        else           asm volatile("cp.async.wait_group 0;\n");
        __syncthreads();       // A(s) + B(s) visible; all prior reads complete
        if (s + 2 < S) load_stage(s + 2);

        const uint32_t SAb = SA0 + (s % 3) * 16384;
        const uint32_t SBb = SB0 + (s & 1) * 16384;
#pragma unroll
        for (int kk16 = 0; kk16 < 32; kk16 += 16) {
            uint32_t bp[4][2];
#pragma unroll
            for (int jp = 0; jp < 2; jp++) {
                int row = n_base + (jp * 2 + jj) * 8 + l7;
                uint32_t off = (uint32_t)(row * 128 + (kk16 + sub * 8) * 2);
                uint32_t r4[4];
                ldm_x4(r4, SBb + SWZ(off));
                bp[jp*2][0] = r4[0]; bp[jp*2][1] = r4[1];
                bp[jp*2+1][0] = r4[2]; bp[jp*2+1][1] = r4[3];
            }
#pragma unroll
            for (int i = 0; i < 4; i++) {
                int row = m_base + i * 16 + l15;
                uint32_t off = (uint32_t)(row * 128 + (kk16 + jj * 8) * 2);
                uint32_t ah[4], al[4];
                ldm_x4(ah, SAb + SWZ(off));
                ldm_x4(al, SAb + SWZ(off + 64));
#pragma unroll
                for (int j = 0; j < 4; j++) {
                    mma_f16(acc[i][j], ah, bp[j]);
                    mma_f16(acc[i][j], al, bp[j]);
                }
            }
        }
        if (s + 1 < S) {
            transform(s + 1, breg);              // writes buf (s+1)&1: disjoint
            if (s + 2 < S) prefetch_b(s + 2, breg);
        }
    }

    // ---- epilogue: transpose -> split-fp16 o^T[hw][ic] ----------------------
    __syncthreads();
    __half* ts = (__half*)smem;                  // [128 n][136]: parity-packed c
    __half* oTh = g_oT_hi + (size_t)b * HW * ICH;
    __half* oTl = g_oT_lo + (size_t)b * HW * ICH;
    const int ic0 = c0 >> 1;
    for (int pass = 0; pass < 2; pass++) {
#pragma unroll
        for (int i = 0; i < 4; i++) {
            int rA = m_base + i * 16 + r;
#pragma unroll
            for (int j = 0; j < 4; j++) {
                int cN = n_base + j * 8 + c2;
#pragma unroll
                for (int q = 0; q < 4; q++) {
                    int rc = rA + (q >> 1) * 8;
                    int cn = cN + (q & 1);
                    float val = acc[i][j][q];
                    __half h = __float2half_rn(val);
                    __half outv = (pass == 0) ? h
                                : __float2half_rn(val - __half2float(h));
                    ts[cn * 136 + (rc & 1) * 64 + (rc >> 1)] = outv;
                }
            }
        }
        __syncthreads();
        {
            int cn = tid >> 1, seg = tid & 1;
            int dstrow = n0 + cn + seg * 2048;       // hw = parity*2048 + n
            __half* dst = (pass == 0 ? oTh : oTl) + (size_t)dstrow * ICH + ic0;
            const uint4* src = (const uint4*)&ts[cn * 136 + seg * 64];
            uint4* d4 = (uint4*)dst;
#pragma unroll
            for (int qq = 0; qq < 8; qq++) d4[qq] = src[qq];
        }
        __syncthreads();
    }
}

// ============================================================================
// Mask MMA kernel:  out[m][hw] = sum_ic w[m][ic]*(oh+ol)[ic][hw] + bias + x.
// A = w fp32->fp16 (in-kernel), B = o^T split fp16, K=128 fully resident.
// smem: A 32KB | Bhi 32KB | Blo 32KB = 96KB -> 2 CTA/SM.
// ============================================================================
#define MK_SMEM_BYTES (3 * 32768)

__global__ __launch_bounds__(256, 2) void mask_mma_kernel(
    const float* __restrict__ wm, const float* __restrict__ bm,
    const float* __restrict__ x, float* __restrict__ outp)
{
    extern __shared__ __align__(128) uint8_t smem[];
    const uint32_t s0 = smem_to_u32(smem);
    const uint32_t SA0 = s0;
    const uint32_t SBh = s0 + 32768;
    const uint32_t SBl = s0 + 65536;

    const int b   = blockIdx.z;
    const int m0  = blockIdx.y * 128;
    const int hw0 = blockIdx.x * 128;
    const int tid  = threadIdx.x;
    const int lane = tid & 31;
    const int w    = tid >> 5;
    const int m_base = (w & 1) * 64;
    const int n_base = (w >> 1) * 32;
    const int r  = lane >> 2;
    const int c2 = (lane & 3) * 2;

    const __half* oTh = g_oT_hi + (size_t)b * HW * ICH;
    const __half* oTl = g_oT_lo + (size_t)b * HW * ICH;

    // A: w fp32 -> fp16, swizzled [128m][region(ic>=64)][64ic]
#pragma unroll
    for (int cch = 0; cch < 8; cch++) {
        int id = tid + cch * 256;           // 2048 16B chunks
        int row = id >> 4, u = id & 15;     // u: 16B chunk within 256B logical row
        const float* src = wm + (size_t)(m0 + row) * ICH + u * 8;
        float4 v0 = *(const float4*)src;
        float4 v1 = *(const float4*)(src + 4);
        uint4 hv = make_uint4(pack_h2(v0.x, v0.y), pack_h2(v0.z, v0.w),
                              pack_h2(v1.x, v1.y), pack_h2(v1.z, v1.w));
        uint32_t dst = SA0 + (u >= 8 ? 16384 : 0)
                     + SWZ((uint32_t)(row * 128 + (u & 7) * 16));
        *(uint4*)(smem + (dst - s0)) = hv;
    }
    // B: o^T hi/lo via cp.async
#pragma unroll
    for (int cch = 0; cch < 8; cch++) {
        int id = tid + cch * 256;
        int row = id >> 4, u = id & 15;
        uint32_t dsw = (u >= 8 ? 16384u : 0u)
                     + SWZ((uint32_t)(row * 128 + (u & 7) * 16));
        const __half* gsrc = oTh + (size_t)(hw0 + row) * ICH + u * 8;
        const __half* gsrl = oTl + (size_t)(hw0 + row) * ICH + u * 8;
        cp_async16(SBh + dsw, gsrc);
        cp_async16(SBl + dsw, gsrl);
    }
    asm volatile("cp.async.commit_group;\n");
    asm volatile("cp.async.wait_group 0;\n");
    __syncthreads();

    float acc[4][4][4];
#pragma unroll
    for (int i = 0; i < 4; i++)
#pragma unroll
        for (int j = 0; j < 4; j++)
#pragma unroll
            for (int q = 0; q < 4; q++) acc[i][j][q] = 0.f;

    const int jj   = lane >> 4;
    const int sub  = (lane >> 3) & 1;
    const int l7   = lane & 7;
    const int l15  = lane & 15;

#pragma unroll
    for (int kt = 0; kt < 8; kt++) {
        const uint32_t reg = (kt >= 4) ? 16384u : 0u;
        uint32_t bh[4][2], bl[4][2];
#pragma unroll
        for (int jp = 0; jp < 2; jp++) {
            int row = n_base + (jp * 2 + jj) * 8 + l7;
            uint32_t off = (uint32_t)(row * 128 + (kt & 3) * 32 + sub * 16);
            uint32_t r4[4];
            ldm_x4(r4, SBh + reg + SWZ(off));
            bh[jp*2][0] = r4[0]; bh[jp*2][1] = r4[1];
            bh[jp*2+1][0] = r4[2]; bh[jp*2+1][1] = r4[3];
            ldm_x4(r4, SBl + reg + SWZ(off));
            bl[jp*2][0] = r4[0]; bl[jp*2][1] = r4[1];
            bl[jp*2+1][0] = r4[2]; bl[jp*2+1][1] = r4[3];
        }
#pragma unroll
        for (int i = 0; i < 4; i++) {
            int row = m_base + i * 16 + l15;
            uint32_t off = (uint32_t)(row * 128 + (kt & 3) * 32 + jj * 16);
            uint32_t ah[4];
            ldm_x4(ah, SA0 + reg + SWZ(off));
#pragma unroll
            for (int j = 0; j < 4; j++) {
                mma_f16(acc[i][j], ah, bh[j]);
                mma_f16(acc[i][j], ah, bl[j]);
            }
        }
    }

    // epilogue: + bias + residual x, write fp32 output
    const float* xr = x    + (size_t)b * CCH * HW;
    float* O        = outp + (size_t)b * CCH * HW;
#pragma unroll
    for (int i = 0; i < 4; i++) {
        int rowA = m0 + m_base + i * 16 + r;
        float bv0 = bm[rowA], bv1 = bm[rowA + 8];
#pragma unroll
        for (int j = 0; j < 4; j++) {
            int col = hw0 + n_base + j * 8 + c2;
            float2 x0 = *(const float2*)&xr[(size_t)rowA * HW + col];
            float2 x1 = *(const float2*)&xr[(size_t)(rowA + 8) * HW + col];
            *(float2*)&O[(size_t)rowA * HW + col] =
                make_float2(acc[i][j][0] + bv0 + x0.x, acc[i][j][1] + bv0 + x0.y);
            *(float2*)&O[(size_t)(rowA + 8) * HW + col] =
                make_float2(acc[i][j][2] + bv1 + x1.x, acc[i][j][3] + bv1 + x1.y);
        }
    }
}

// ============================================================================
// Kernel 1: projections (fp32 FFMA GEMM) + split-fp16 epilogues.
// ============================================================================
union ProjSmem {
    struct { float As[BK][BM + 4]; float Bs[BK][BN]; } g;
    __half t[128][136];
};

__global__ __launch_bounds__(256) void proj_kernel(
    const float* __restrict__ x,
    const float* __restrict__ w0, const float* __restrict__ b0,
    const float* __restrict__ w1, const float* __restrict__ b1,
    const float* __restrict__ w2, const float* __restrict__ b2)
{
    const int z = blockIdx.z;
    const int batch = z / 3;
    const int pj = z - batch * 3;
    const float* W    = (pj == 0) ? w0 : (pj == 1) ? w1 : w2;
    const float* bias = (pj == 0) ? b0 : (pj == 1) ? b1 : b2;
    const float* Bmat = x + (size_t)batch * CCH * HW;

    const int K = CCH, N = HW;
    const int n0 = blockIdx.x * BN;

    __shared__ ProjSmem sm;

    const int tid = threadIdx.x;
    const int tx = tid & 15, ty = tid >> 4;

    float acc[8][8];
#pragma unroll
    for (int i = 0; i < 8; i++)
#pragma unroll
        for (int j = 0; j < 8; j++) acc[i][j] = 0.f;

    for (int k0 = 0; k0 < K; k0 += BK) {
#pragma unroll
        for (int u = 0; u < 2; u++) {
            int idx = tid + u * 256;
            int rr = idx >> 2, cq = idx & 3;
            float4 v = *(const float4*)&W[rr * K + k0 + cq * 4];
            sm.g.As[cq*4+0][rr] = v.x; sm.g.As[cq*4+1][rr] = v.y;
            sm.g.As[cq*4+2][rr] = v.z; sm.g.As[cq*4+3][rr] = v.w;
        }
#pragma unroll
        for (int u = 0; u < 2; u++) {
            int idx = tid + u * 256;
            int kk = idx >> 5, nq = idx & 31;
            *(float4*)&sm.g.Bs[kk][nq*4] =
                *(const float4*)&Bmat[(size_t)(k0+kk)*N + n0 + nq*4];
        }
        __syncthreads();
#pragma unroll
        for (int kk = 0; kk < BK; kk++) {
            float a[8], bb[8];
            *(float4*)&a[0] = *(const float4*)&sm.g.As[kk][ty*4];
            *(float4*)&a[4] = *(const float4*)&sm.g.As[kk][64 + ty*4];
            *(float4*)&bb[0] = *(const float4*)&sm.g.Bs[kk][tx*4];
            *(float4*)&bb[4] = *(const float4*)&sm.g.Bs[kk][64 + tx*4];
#pragma unroll
            for (int i = 0; i < 8; i++)
#pragma unroll
                for (int j = 0; j < 8; j++) acc[i][j] += a[i] * bb[j];
        }
        __syncthreads();
    }

#pragma unroll
    for (int i = 0; i < 8; i++) {
        int m = (i < 4) ? (ty*4 + i) : (64 + ty*4 + i - 4);
        float bv = bias[m];
#pragma unroll
        for (int j = 0; j < 8; j++) acc[i][j] += bv;
    }

    const int half = n0 / 2048;
    const int nr0  = n0 - half * 2048;

    if (pj == 2) {
        __half* gh = g_g_hi + (size_t)batch * CCH * NV;
        __half* gl = g_g_lo + (size_t)batch * CCH * NV;
#pragma unroll
        for (int i = 0; i < 8; i++) {
            int ic = (i < 4) ? (ty*4 + i) : (64 + ty*4 + i - 4);
            int c = 2*ic + half;
#pragma unroll
            for (int jg = 0; jg < 2; jg++) {
                int colb = nr0 + jg*64 + tx*4;
                uint2 hv, lv;
                split2(acc[i][jg*4+0], acc[i][jg*4+1], hv.x, lv.x);
                split2(acc[i][jg*4+2], acc[i][jg*4+3], hv.y, lv.y);
                *(uint2*)&gh[(size_t)c*NV + colb] = hv;
                *(uint2*)&gl[(size_t)c*NV + colb] = lv;
            }
        }
    } else {
        __half* Thi = ((pj == 0) ? g_phT_hi : g_thT_hi) + (size_t)batch * NV * CCH;
        __half* Tlo = ((pj == 0) ? g_phT_lo : g_thT_lo) + (size_t)batch * NV * CCH;

        for (int pass = 0; pass < 2; pass++) {
#pragma unroll
            for (int i = 0; i < 8; i++) {
                int m = (i < 4) ? (ty*4 + i) : (64 + ty*4 + i - 4);
#pragma unroll
                for (int j = 0; j < 8; j++) {
                    int col = (j < 4) ? (tx*4 + j) : (64 + tx*4 + j - 4);
                    float v = acc[i][j];
                    __half h = __float2half_rn(v);
                    sm.t[col][m] = (pass == 0) ? h
                                 : __float2half_rn(v - __half2float(h));
                }
            }
            __syncthreads();
            {
                int row = tid >> 1, seg = tid & 1;
                __half* dstb = (pass == 0 ? Thi : Tlo)
                    + (size_t)(nr0 + row) * CCH + half*128 + seg*64;
                const uint4* src = (const uint4*)&sm.t[row][seg*64];
                uint4* dst = (uint4*)dstb;
#pragma unroll
                for (int q = 0; q < 8; q++) dst[q] = src[q];
            }
            __syncthreads();
        }
    }
}

// ============================================================================
// Kernel 3: per-column (m) online softmax stats over rows n.
// ============================================================================
__global__ __launch_bounds__(256) void reduce_kernel()
{
    const int b = blockIdx.y;
    const int m = blockIdx.x * 256 + threadIdx.x;
    const float* S = g_s + (size_t)b * NV * NV;

    float mx = __int_as_float(0xff800000);
    float sm = 0.f;
    for (int n = 0; n < NV; n += 8) {
        float v[8];
#pragma unroll
        for (int q = 0; q < 8; q++) v[q] = S[(size_t)(n+q)*NV + m];
#pragma unroll
        for (int q = 0; q < 8; q++) {
            float nm = fmaxf(mx, v[q]);
            sm = sm * expf(mx - nm) + expf(v[q] - nm);
            mx = nm;
        }
    }
    g_cmax[b*NV + m] = mx;
    g_cinv[b*NV + m] = 1.0f / sm;
}

// ============================================================================
extern "C" void kernel_launch(void* const* d_in, const int* in_sizes, int n_in,
                              void* d_out, int out_size)
{
    const float* x       = (const float*)d_in[0];
    const float* w_phi   = (const float*)d_in[1];
    const float* b_phi   = (const float*)d_in[2];
    const float* w_theta = (const float*)d_in[3];
    const float* b_theta = (const float*)d_in[4];
    const float* w_g     = (const float*)d_in[5];
    const float* b_g     = (const float*)d_in[6];
    const float* w_mask  = (const float*)d_in[7];
    const float* b_mask  = (const float*)d_in[8];
    float* out = (float*)d_out;

    __half *thT_hi, *thT_lo, *phT_hi, *phT_lo;
    float *sptr;
    cudaGetSymbolAddress((void**)&thT_hi, g_thT_hi);
    cudaGetSymbolAddress((void**)&thT_lo, g_thT_lo);
    cudaGetSymbolAddress((void**)&phT_hi, g_phT_hi);
    cudaGetSymbolAddress((void**)&phT_lo, g_phT_lo);
    cudaGetSymbolAddress((void**)&sptr,   g_s);

    cudaFuncSetAttribute(mma_gemm_kernel,
                         cudaFuncAttributeMaxDynamicSharedMemorySize, SC_SMEM_BYTES);
    cudaFuncSetAttribute(outgemm_fused_kernel,
                         cudaFuncAttributeMaxDynamicSharedMemorySize, OG_SMEM_BYTES);
    cudaFuncSetAttribute(mask_mma_kernel,
                         cudaFuncAttributeMaxDynamicSharedMemorySize, MK_SMEM_BYTES);

    // 1) projections -> split-fp16 operands
    proj_kernel<<<dim3(HW/BN, 1, BATCH*3), 256>>>(x, w_phi, b_phi,
                                                   w_theta, b_theta, w_g, b_g);
    // 2) scores: S[n][m] = theta^T . phi   (M=N=2048, K=256), fp32 out
    mma_gemm_kernel<<<dim3(16, 16, BATCH), 256, SC_SMEM_BYTES>>>(
        thT_hi, thT_lo, phT_hi, phT_lo, sptr, CCH,
        (size_t)NV*CCH, (size_t)NV*CCH, (size_t)NV*NV);
    // 3) column softmax stats
    reduce_kernel<<<dim3(NV/256, BATCH), 256>>>();
    // 4) fused outgemm -> split-fp16 o^T
    outgemm_fused_kernel<<<dim3(16, 2, BATCH), 256, OG_SMEM_BYTES>>>();
    // 5) mask conv (fp16 MMA) + bias + residual
    mask_mma_kernel<<<dim3(HW/128, CCH/128, BATCH), 256, MK_SMEM_BYTES>>>(
        w_mask, b_mask, x, out);
}